// round 4
// baseline (speedup 1.0000x reference)
#include <cuda_runtime.h>
#include <math.h>
#include <stdint.h>

#define BATCH 16384
#define SEQ   50
#define DIM   300
#define HID   32
#define OUTC  2
#define VOCAB 400000

// allocation-free scratch
__device__ float g_lse[2];
__device__ float g_E2[(size_t)VOCAB * HID];   // 51.2 MB projected table

// ---------------------------------------------------------------------------
// Pass A: E2[v][j] = sum_d emb[v][d] * Vw[j][d]   (400000x300 @ 300x32)
// tf32 mma.sync m16n8k8. Persistent CTAs (148), 256 threads, 64-row tiles.
// Tile load = ONE cp.async.bulk (UBLKCP) per tile + mbarrier complete_tx,
// double-buffered. Packed A rows (stride 300) are conflict-free for the
// fragment LDS pattern (bank = (g4*12+tg) mod 32, all distinct).
// ---------------------------------------------------------------------------
#define TILE_R     64
#define KSTEPS     38                        // ceil(300/8); tail k>=300 hits zero B
#define NT_TILES   (VOCAB / TILE_R)          // 6250
#define TILE_ELEMS (TILE_R * DIM)            // 19200 floats
#define TILE_BYTES (TILE_ELEMS * 4)          // 76800 B
#define PAD_ELEMS  16                        // zeroed pad after each stage
#define STAGE_ELEMS (TILE_ELEMS + PAD_ELEMS) // 19216
#define B_ELEMS    (KSTEPS * 4 * 2 * 32)     // 9728 floats
// layout: sA0 | sA1 | sB | 2 mbarriers (8B each, 16B aligned)
#define MBAR_OFF   (2 * STAGE_ELEMS + B_ELEMS)          // float index, 16B aligned
#define SMEM_BYTES ((MBAR_OFF + 4) * 4)                 // + 16 B for 2 mbarriers

__device__ __forceinline__ uint32_t smem_u32(const void* p) {
    return (uint32_t)__cvta_generic_to_shared(p);
}

__device__ __forceinline__ void mbar_init(uint32_t mbar, uint32_t cnt) {
    asm volatile("mbarrier.init.shared::cta.b64 [%0], %1;" :: "r"(mbar), "r"(cnt) : "memory");
}
__device__ __forceinline__ void mbar_expect_tx(uint32_t mbar, uint32_t bytes) {
    asm volatile("mbarrier.arrive.expect_tx.shared::cta.b64 _, [%0], %1;"
                 :: "r"(mbar), "r"(bytes) : "memory");
}
__device__ __forceinline__ void mbar_wait(uint32_t mbar, uint32_t parity) {
    asm volatile(
        "{\n\t"
        ".reg .pred P;\n\t"
        "WAIT_%=: \n\t"
        "mbarrier.try_wait.parity.acquire.cta.shared::cta.b64 P, [%0], %1, 0x989680;\n\t"
        "@P bra.uni DONE_%=;\n\t"
        "bra.uni WAIT_%=;\n\t"
        "DONE_%=: \n\t"
        "}"
        :: "r"(mbar), "r"(parity) : "memory");
}
__device__ __forceinline__ void bulk_copy(uint32_t dst, const void* src,
                                          uint32_t bytes, uint32_t mbar) {
    asm volatile(
        "cp.async.bulk.shared::cta.global.mbarrier::complete_tx::bytes "
        "[%0], [%1], %2, [%3];"
        :: "r"(dst), "l"(src), "r"(bytes), "r"(mbar) : "memory");
}

__global__ __launch_bounds__(256) void project_kernel(
    const float* __restrict__ emb,
    const float* __restrict__ Vw)
{
    extern __shared__ float smem[];
    float*    sA[2] = { smem, smem + STAGE_ELEMS };
    uint32_t* sB    = (uint32_t*)(smem + 2 * STAGE_ELEMS);
    const uint32_t mbar0 = smem_u32(smem + MBAR_OFF);
    const uint32_t mbar1 = mbar0 + 8;

    const int tid  = threadIdx.x;
    const int warp = tid >> 5;
    const int lane = tid & 31;
    const int g4   = lane >> 2;
    const int tg   = lane & 3;

    // init barriers, then kick off first tile load ASAP
    if (tid == 0) {
        mbar_init(mbar0, 1);
        mbar_init(mbar1, 1);
        asm volatile("fence.proxy.async.shared::cta;" ::: "memory");
    }
    __syncthreads();

    int t = blockIdx.x;
    if (tid == 0 && t < NT_TILES) {
        mbar_expect_tx(mbar0, TILE_BYTES);
        bulk_copy(smem_u32(sA[0]), emb + (size_t)t * TILE_ELEMS, TILE_BYTES, mbar0);
    }

    // fill B fragments once (pre-converted to tf32), zero-padded past k=299
    for (int i = tid; i < B_ELEMS; i += 256) {
        int l  = i & 31;
        int h  = (i >> 5) & 1;
        int nt = (i >> 6) & 3;
        int ks = i >> 8;
        int k  = ks * 8 + h * 4 + (l & 3);
        int n  = nt * 8 + (l >> 2);
        float v = (k < DIM) ? Vw[n * DIM + k] : 0.0f;
        uint32_t b;
        asm("cvt.rna.tf32.f32 %0, %1;" : "=r"(b) : "f"(v));
        sB[i] = b;
    }
    // zero the pads after each stage (never overwritten by bulk copies)
    if (tid < PAD_ELEMS) {
        sA[0][TILE_ELEMS + tid] = 0.0f;
        sA[1][TILE_ELEMS + tid] = 0.0f;
    }
    __syncthreads();

    const int warpRow = warp >> 1;                // 0..3
    const int colHalf = warp & 1;                 // 0/1
    const int aRow    = warpRow * 16 + g4;

    int stage = 0;
    uint32_t ph[2] = {0, 0};
    const uint32_t mbars[2] = {mbar0, mbar1};

    for (; t < NT_TILES; t += gridDim.x) {
        int tn = t + gridDim.x;
        // stage^1 was fully consumed before the trailing __syncthreads of the
        // previous iteration -> safe to refill now.
        if (tid == 0 && tn < NT_TILES) {
            mbar_expect_tx(mbars[stage ^ 1], TILE_BYTES);
            bulk_copy(smem_u32(sA[stage ^ 1]), emb + (size_t)tn * TILE_ELEMS,
                      TILE_BYTES, mbars[stage ^ 1]);
        }

        mbar_wait(mbars[stage], ph[stage]);
        ph[stage] ^= 1;

        const float* A = sA[stage];

        float c0[2] = {0.f, 0.f}, c1[2] = {0.f, 0.f};
        float c2[2] = {0.f, 0.f}, c3[2] = {0.f, 0.f};

        #pragma unroll 2
        for (int ks = 0; ks < KSTEPS; ks++) {
            const float* ap = &A[aRow * DIM + ks * 8 + tg];
            float a0f = ap[0];
            float a1f = ap[8 * DIM];
            float a2f = ap[4];
            float a3f = ap[8 * DIM + 4];
            uint32_t a0, a1, a2, a3;
            asm("cvt.rna.tf32.f32 %0, %1;" : "=r"(a0) : "f"(a0f));
            asm("cvt.rna.tf32.f32 %0, %1;" : "=r"(a1) : "f"(a1f));
            asm("cvt.rna.tf32.f32 %0, %1;" : "=r"(a2) : "f"(a2f));
            asm("cvt.rna.tf32.f32 %0, %1;" : "=r"(a3) : "f"(a3f));

            #pragma unroll
            for (int s = 0; s < 2; s++) {
                int nt = colHalf * 2 + s;
                uint32_t b0 = sB[((ks * 4 + nt) * 2 + 0) * 32 + lane];
                uint32_t b1 = sB[((ks * 4 + nt) * 2 + 1) * 32 + lane];
                asm volatile(
                    "mma.sync.aligned.m16n8k8.row.col.f32.tf32.tf32.f32 "
                    "{%0,%1,%2,%3}, {%4,%5,%6,%7}, {%8,%9}, {%0,%1,%2,%3};\n"
                    : "+f"(c0[s]), "+f"(c1[s]), "+f"(c2[s]), "+f"(c3[s])
                    : "r"(a0), "r"(a1), "r"(a2), "r"(a3), "r"(b0), "r"(b1));
            }
        }

        // store 16x16 per warp (float2 stores)
        int rbase = t * TILE_R + warpRow * 16;
        #pragma unroll
        for (int s = 0; s < 2; s++) {
            int col = colHalf * 16 + s * 8 + tg * 2;
            int r0  = rbase + g4;
            *(float2*)&g_E2[(size_t)r0 * HID + col]       = make_float2(c0[s], c1[s]);
            *(float2*)&g_E2[(size_t)(r0 + 8) * HID + col] = make_float2(c2[s], c3[s]);
        }

        __syncthreads();   // all warps done reading this stage before refill
        stage ^= 1;
    }
}

// ---------------------------------------------------------------------------
// Pass B: gather E2 rows, mean-pool, relu MLP head -> logits.
// One warp per batch row; lane = hidden unit. 128B coalesced gathers.
// ---------------------------------------------------------------------------
__global__ __launch_bounds__(256) void gather_kernel(
    const int*   __restrict__ tokens,
    const float* __restrict__ Vb,
    const float* __restrict__ Ww,
    const float* __restrict__ Wb,
    float*       __restrict__ out)
{
    const int b    = blockIdx.x * 8 + (threadIdx.x >> 5);
    const int lane = threadIdx.x & 31;

    int t0 = tokens[b * SEQ + lane];
    int t1 = (lane < SEQ - 32) ? tokens[b * SEQ + 32 + lane] : 0;

    float acc = 0.f;
    #pragma unroll
    for (int k = 0; k < SEQ; k++) {
        int tok = (k < 32) ? __shfl_sync(0xffffffffu, t0, k)
                           : __shfl_sync(0xffffffffu, t1, k - 32);
        acc += __ldg(&g_E2[(size_t)tok * HID + lane]);
    }

    float h  = fmaxf(acc * (1.0f / (float)SEQ) + Vb[lane], 0.f);
    float p0 = h * Ww[lane];          // Ww[0][lane]
    float p1 = h * Ww[HID + lane];    // Ww[1][lane]
    #pragma unroll
    for (int off = 16; off; off >>= 1) {
        p0 += __shfl_xor_sync(0xffffffffu, p0, off);
        p1 += __shfl_xor_sync(0xffffffffu, p1, off);
    }
    if (lane == 0) {
        out[b * OUTC + 0] = p0 + Wb[0];
        out[b * OUTC + 1] = p1 + Wb[1];
    }
}

// ---------------------------------------------------------------------------
// Pass C: column-wise logsumexp over the batch axis + in-place subtract.
// Single CTA (fused lse + apply).
// ---------------------------------------------------------------------------
__global__ __launch_bounds__(1024) void lse_apply_kernel(float* __restrict__ logits)
{
    __shared__ float2 red[1024];
    const int tid = threadIdx.x;

    float m0 = -1e30f, m1 = -1e30f;
    for (int r = tid; r < BATCH; r += 1024) {
        float2 v = reinterpret_cast<const float2*>(logits)[r];
        m0 = fmaxf(m0, v.x);
        m1 = fmaxf(m1, v.y);
    }
    red[tid] = make_float2(m0, m1);
    __syncthreads();
    for (int s = 512; s; s >>= 1) {
        if (tid < s) {
            red[tid].x = fmaxf(red[tid].x, red[tid + s].x);
            red[tid].y = fmaxf(red[tid].y, red[tid + s].y);
        }
        __syncthreads();
    }
    m0 = red[0].x; m1 = red[0].y;
    __syncthreads();

    float s0 = 0.f, s1 = 0.f;
    for (int r = tid; r < BATCH; r += 1024) {
        float2 v = reinterpret_cast<const float2*>(logits)[r];
        s0 += expf(v.x - m0);
        s1 += expf(v.y - m1);
    }
    red[tid] = make_float2(s0, s1);
    __syncthreads();
    for (int s = 512; s; s >>= 1) {
        if (tid < s) {
            red[tid].x += red[tid + s].x;
            red[tid].y += red[tid + s].y;
        }
        __syncthreads();
    }
    __syncthreads();
    const float l0 = m0 + logf(red[0].x);
    const float l1 = m1 + logf(red[0].y);

    for (int r = tid; r < BATCH; r += 1024) {
        float2 v = reinterpret_cast<float2*>(logits)[r];
        v.x -= l0;
        v.y -= l1;
        reinterpret_cast<float2*>(logits)[r] = v;
    }
}

extern "C" void kernel_launch(void* const* d_in, const int* in_sizes, int n_in,
                              void* d_out, int out_size)
{
    const int*   tokens = (const int*)  d_in[0];
    const float* emb    = (const float*)d_in[1];
    const float* Vw     = (const float*)d_in[2];
    const float* Vb     = (const float*)d_in[3];
    const float* Ww     = (const float*)d_in[4];
    const float* Wb     = (const float*)d_in[5];
    float* out = (float*)d_out;

    cudaFuncSetAttribute(project_kernel,
                         cudaFuncAttributeMaxDynamicSharedMemorySize, SMEM_BYTES);

    project_kernel<<<148, 256, SMEM_BYTES>>>(emb, Vw);
    gather_kernel<<<BATCH / 8, 256>>>(tokens, Vb, Ww, Wb, out);
    lse_apply_kernel<<<1, 1024>>>(out);
}

// round 5
// speedup vs baseline: 1.1912x; 1.1912x over previous
#include <cuda_runtime.h>
#include <math.h>
#include <stdint.h>

#define BATCH 16384
#define SEQ   50
#define DIM   300
#define HID   32
#define OUTC  2
#define VOCAB 400000

// allocation-free scratch
__device__ float g_E2[(size_t)VOCAB * HID];   // 51.2 MB projected table

// ---------------------------------------------------------------------------
// Pass A: E2[v][j] = sum_d emb[v][d] * Vw[j][d]   (400000x300 @ 300x32)
// tf32 mma.sync m16n8k8, raw fp32 bits fed as tf32 (RZ truncation, no cvt).
// Persistent CTAs (148), 256 threads, 64-row tiles, one cp.async.bulk per
// tile + mbarrier, double buffered. B fragments pre-packed as per-lane uint2
// so each kstep needs: 4x LDS.32 (A) + 1x LDS.64 (B) + 2x MMA.
// ---------------------------------------------------------------------------
#define TILE_R     64
#define KSTEPS     38                        // ceil(300/8); k>=300 hits zero B
#define NT_TILES   (VOCAB / TILE_R)          // 6250
#define TILE_ELEMS (TILE_R * DIM)            // 19200 floats
#define TILE_BYTES (TILE_ELEMS * 4)          // 76800 B
#define PAD_ELEMS  16                        // zeroed pad after each stage
#define STAGE_ELEMS (TILE_ELEMS + PAD_ELEMS) // 19216
#define B_PAIRS    (KSTEPS * 4 * 32)         // 4864 uint2 = 38912 B
// layout: sA0 | sA1 | sB(uint2) | 2 mbarriers
#define MBAR_OFF   (2 * STAGE_ELEMS + 2 * B_PAIRS)      // float index (16B aligned)
#define SMEM_BYTES ((MBAR_OFF + 4) * 4)

__device__ __forceinline__ uint32_t smem_u32(const void* p) {
    return (uint32_t)__cvta_generic_to_shared(p);
}
__device__ __forceinline__ void mbar_init(uint32_t mbar, uint32_t cnt) {
    asm volatile("mbarrier.init.shared::cta.b64 [%0], %1;" :: "r"(mbar), "r"(cnt) : "memory");
}
__device__ __forceinline__ void mbar_expect_tx(uint32_t mbar, uint32_t bytes) {
    asm volatile("mbarrier.arrive.expect_tx.shared::cta.b64 _, [%0], %1;"
                 :: "r"(mbar), "r"(bytes) : "memory");
}
__device__ __forceinline__ void mbar_wait(uint32_t mbar, uint32_t parity) {
    asm volatile(
        "{\n\t"
        ".reg .pred P;\n\t"
        "WAIT_%=: \n\t"
        "mbarrier.try_wait.parity.acquire.cta.shared::cta.b64 P, [%0], %1, 0x989680;\n\t"
        "@P bra.uni DONE_%=;\n\t"
        "bra.uni WAIT_%=;\n\t"
        "DONE_%=: \n\t"
        "}"
        :: "r"(mbar), "r"(parity) : "memory");
}
__device__ __forceinline__ void bulk_copy(uint32_t dst, const void* src,
                                          uint32_t bytes, uint32_t mbar) {
    asm volatile(
        "cp.async.bulk.shared::cta.global.mbarrier::complete_tx::bytes "
        "[%0], [%1], %2, [%3];"
        :: "r"(dst), "l"(src), "r"(bytes), "r"(mbar) : "memory");
}

__global__ __launch_bounds__(256) void project_kernel(
    const float* __restrict__ emb,
    const float* __restrict__ Vw)
{
    extern __shared__ float smem[];
    float* sA[2] = { smem, smem + STAGE_ELEMS };
    uint2* sB    = (uint2*)(smem + 2 * STAGE_ELEMS);
    const uint32_t mbar0 = smem_u32(smem + MBAR_OFF);
    const uint32_t mbar1 = mbar0 + 8;

    const int tid  = threadIdx.x;
    const int warp = tid >> 5;
    const int lane = tid & 31;
    const int g4   = lane >> 2;
    const int tg   = lane & 3;

    if (tid == 0) {
        mbar_init(mbar0, 1);
        mbar_init(mbar1, 1);
        asm volatile("fence.proxy.async.shared::cta;" ::: "memory");
    }
    __syncthreads();

    int t = blockIdx.x;
    if (tid == 0 && t < NT_TILES) {
        mbar_expect_tx(mbar0, TILE_BYTES);
        bulk_copy(smem_u32(sA[0]), emb + (size_t)t * TILE_ELEMS, TILE_BYTES, mbar0);
    }

    // Pack B fragment pairs once: sB[(ks*4+nt)*32 + lane] = {bits(Vw[n][k]),
    // bits(Vw[n][k+4])} with n = nt*8 + lane/4, k = ks*8 + lane%4.
    // Raw fp32 bits (tf32 mma truncates mantissa). Zero for k >= 300.
    for (int i = tid; i < B_PAIRS; i += 256) {
        int l  = i & 31;
        int nt = (i >> 5) & 3;
        int ks = i >> 7;
        int k  = ks * 8 + (l & 3);
        int n  = nt * 8 + (l >> 2);
        uint2 v;
        v.x = (k     < DIM) ? __float_as_uint(Vw[n * DIM + k])     : 0u;
        v.y = (k + 4 < DIM) ? __float_as_uint(Vw[n * DIM + k + 4]) : 0u;
        sB[i] = v;
    }
    if (tid < PAD_ELEMS) {
        sA[0][TILE_ELEMS + tid] = 0.0f;
        sA[1][TILE_ELEMS + tid] = 0.0f;
    }
    __syncthreads();

    const int warpRow = warp >> 1;               // 0..3
    const int colHalf = warp & 1;                // 0/1
    const int aRow    = warpRow * 16 + g4;

    int stage = 0;
    uint32_t ph[2] = {0, 0};
    const uint32_t mbars[2] = {mbar0, mbar1};

    for (; t < NT_TILES; t += gridDim.x) {
        int tn = t + gridDim.x;
        if (tid == 0 && tn < NT_TILES) {
            mbar_expect_tx(mbars[stage ^ 1], TILE_BYTES);
            bulk_copy(smem_u32(sA[stage ^ 1]), emb + (size_t)tn * TILE_ELEMS,
                      TILE_BYTES, mbars[stage ^ 1]);
        }

        mbar_wait(mbars[stage], ph[stage]);
        ph[stage] ^= 1;

        const uint32_t* A = (const uint32_t*)sA[stage] + aRow * DIM + tg;
        const uint2*    B = sB + (colHalf * 2) * 32 + lane;

        float c0[2] = {0.f, 0.f}, c1[2] = {0.f, 0.f};
        float c2[2] = {0.f, 0.f}, c3[2] = {0.f, 0.f};

        // software-pipelined: prefetch kstep+1 while mma'ing kstep
        uint32_t a0 = A[0], a1 = A[8 * DIM], a2 = A[4], a3 = A[8 * DIM + 4];
        uint2    b0 = B[0], b1 = B[32];

        #pragma unroll 2
        for (int ks = 0; ks < KSTEPS; ks++) {
            uint32_t na0, na1, na2, na3;
            uint2    nb0, nb1;
            if (ks + 1 < KSTEPS) {
                const uint32_t* Ap = A + (ks + 1) * 8;
                na0 = Ap[0]; na1 = Ap[8 * DIM]; na2 = Ap[4]; na3 = Ap[8 * DIM + 4];
                const uint2* Bp = B + (ks + 1) * 4 * 32;
                nb0 = Bp[0]; nb1 = Bp[32];
            }
            asm volatile(
                "mma.sync.aligned.m16n8k8.row.col.f32.tf32.tf32.f32 "
                "{%0,%1,%2,%3}, {%4,%5,%6,%7}, {%8,%9}, {%0,%1,%2,%3};\n"
                : "+f"(c0[0]), "+f"(c1[0]), "+f"(c2[0]), "+f"(c3[0])
                : "r"(a0), "r"(a1), "r"(a2), "r"(a3), "r"(b0.x), "r"(b0.y));
            asm volatile(
                "mma.sync.aligned.m16n8k8.row.col.f32.tf32.tf32.f32 "
                "{%0,%1,%2,%3}, {%4,%5,%6,%7}, {%8,%9}, {%0,%1,%2,%3};\n"
                : "+f"(c0[1]), "+f"(c1[1]), "+f"(c2[1]), "+f"(c3[1])
                : "r"(a0), "r"(a1), "r"(a2), "r"(a3), "r"(b1.x), "r"(b1.y));
            a0 = na0; a1 = na1; a2 = na2; a3 = na3;
            b0 = nb0; b1 = nb1;
        }

        // store 16x16 per warp (float2 stores)
        int rbase = t * TILE_R + warpRow * 16;
        #pragma unroll
        for (int s = 0; s < 2; s++) {
            int col = colHalf * 16 + s * 8 + tg * 2;
            int r0  = rbase + g4;
            *(float2*)&g_E2[(size_t)r0 * HID + col]       = make_float2(c0[s], c1[s]);
            *(float2*)&g_E2[(size_t)(r0 + 8) * HID + col] = make_float2(c2[s], c3[s]);
        }

        __syncthreads();   // all warps done with this stage before refill
        stage ^= 1;
    }
}

// ---------------------------------------------------------------------------
// Pass B: gather E2 rows, mean-pool, relu MLP head -> logits.
// One warp per batch row; lane = hidden unit. 128B coalesced gathers.
// ---------------------------------------------------------------------------
__global__ __launch_bounds__(256) void gather_kernel(
    const int*   __restrict__ tokens,
    const float* __restrict__ Vb,
    const float* __restrict__ Ww,
    const float* __restrict__ Wb,
    float*       __restrict__ out)
{
    const int b    = blockIdx.x * 8 + (threadIdx.x >> 5);
    const int lane = threadIdx.x & 31;

    int t0 = tokens[b * SEQ + lane];
    int t1 = (lane < SEQ - 32) ? tokens[b * SEQ + 32 + lane] : 0;

    float acc = 0.f;
    #pragma unroll
    for (int k = 0; k < SEQ; k++) {
        int tok = (k < 32) ? __shfl_sync(0xffffffffu, t0, k)
                           : __shfl_sync(0xffffffffu, t1, k - 32);
        acc += __ldg(&g_E2[(size_t)tok * HID + lane]);
    }

    float h  = fmaxf(acc * (1.0f / (float)SEQ) + Vb[lane], 0.f);
    float p0 = h * Ww[lane];          // Ww[0][lane]
    float p1 = h * Ww[HID + lane];    // Ww[1][lane]
    #pragma unroll
    for (int off = 16; off; off >>= 1) {
        p0 += __shfl_xor_sync(0xffffffffu, p0, off);
        p1 += __shfl_xor_sync(0xffffffffu, p1, off);
    }
    if (lane == 0) {
        out[b * OUTC + 0] = p0 + Wb[0];
        out[b * OUTC + 1] = p1 + Wb[1];
    }
}

// ---------------------------------------------------------------------------
// Pass C: column-wise logsumexp over the batch axis + in-place subtract.
// Single CTA (fused lse + apply).
// ---------------------------------------------------------------------------
__global__ __launch_bounds__(1024) void lse_apply_kernel(float* __restrict__ logits)
{
    __shared__ float2 red[1024];
    const int tid = threadIdx.x;

    float m0 = -1e30f, m1 = -1e30f;
    for (int r = tid; r < BATCH; r += 1024) {
        float2 v = reinterpret_cast<const float2*>(logits)[r];
        m0 = fmaxf(m0, v.x);
        m1 = fmaxf(m1, v.y);
    }
    red[tid] = make_float2(m0, m1);
    __syncthreads();
    for (int s = 512; s; s >>= 1) {
        if (tid < s) {
            red[tid].x = fmaxf(red[tid].x, red[tid + s].x);
            red[tid].y = fmaxf(red[tid].y, red[tid + s].y);
        }
        __syncthreads();
    }
    m0 = red[0].x; m1 = red[0].y;
    __syncthreads();

    float s0 = 0.f, s1 = 0.f;
    for (int r = tid; r < BATCH; r += 1024) {
        float2 v = reinterpret_cast<const float2*>(logits)[r];
        s0 += expf(v.x - m0);
        s1 += expf(v.y - m1);
    }
    red[tid] = make_float2(s0, s1);
    __syncthreads();
    for (int s = 512; s; s >>= 1) {
        if (tid < s) {
            red[tid].x += red[tid + s].x;
            red[tid].y += red[tid + s].y;
        }
        __syncthreads();
    }
    __syncthreads();
    const float l0 = m0 + logf(red[0].x);
    const float l1 = m1 + logf(red[0].y);

    for (int r = tid; r < BATCH; r += 1024) {
        float2 v = reinterpret_cast<float2*>(logits)[r];
        v.x -= l0;
        v.y -= l1;
        reinterpret_cast<float2*>(logits)[r] = v;
    }
}

extern "C" void kernel_launch(void* const* d_in, const int* in_sizes, int n_in,
                              void* d_out, int out_size)
{
    const int*   tokens = (const int*)  d_in[0];
    const float* emb    = (const float*)d_in[1];
    const float* Vw     = (const float*)d_in[2];
    const float* Vb     = (const float*)d_in[3];
    const float* Ww     = (const float*)d_in[4];
    const float* Wb     = (const float*)d_in[5];
    float* out = (float*)d_out;

    cudaFuncSetAttribute(project_kernel,
                         cudaFuncAttributeMaxDynamicSharedMemorySize, SMEM_BYTES);

    project_kernel<<<148, 256, SMEM_BYTES>>>(emb, Vw);
    gather_kernel<<<BATCH / 8, 256>>>(tokens, Vb, Ww, Wb, out);
    lse_apply_kernel<<<1, 1024>>>(out);
}

// round 6
// speedup vs baseline: 1.2473x; 1.0471x over previous
#include <cuda_runtime.h>
#include <math.h>
#include <stdint.h>

#define BATCH 16384
#define SEQ   50
#define DIM   300
#define HID   32
#define OUTC  2
#define VOCAB 400000

// allocation-free scratch
__device__ float g_E2[(size_t)VOCAB * HID];   // 51.2 MB projected table

// ---------------------------------------------------------------------------
// Pass A: E2[v][j] = sum_d emb[v][d] * Vw[j][d]   (400000x300 @ 300x32)
// tf32 mma.sync m16n8k8, raw fp32 bits fed as tf32 (RZ truncation, no cvt).
// Persistent CTAs (148), 256 threads, 64-row tiles, one cp.async.bulk per
// tile + mbarrier, double buffered.
// K split into even/odd phases with separate accumulators -> 4 independent
// MMA chains per warp; k-loop fully unrolled (huge reg headroom at occ 12.5%).
// ---------------------------------------------------------------------------
#define TILE_R     64
#define KSTEPS     38                        // ceil(300/8); k>=300 hits zero B
#define NT_TILES   (VOCAB / TILE_R)          // 6250
#define TILE_ELEMS (TILE_R * DIM)            // 19200 floats
#define TILE_BYTES (TILE_ELEMS * 4)          // 76800 B
#define PAD_ELEMS  16                        // zeroed pad after each stage
#define STAGE_ELEMS (TILE_ELEMS + PAD_ELEMS) // 19216
#define B_PAIRS    (KSTEPS * 4 * 32)         // 4864 uint2 = 38912 B
// layout: sA0 | sA1 | sB(uint2) | 2 mbarriers
#define MBAR_OFF   (2 * STAGE_ELEMS + 2 * B_PAIRS)      // float index (16B aligned)
#define SMEM_BYTES ((MBAR_OFF + 4) * 4)

__device__ __forceinline__ uint32_t smem_u32(const void* p) {
    return (uint32_t)__cvta_generic_to_shared(p);
}
__device__ __forceinline__ void mbar_init(uint32_t mbar, uint32_t cnt) {
    asm volatile("mbarrier.init.shared::cta.b64 [%0], %1;" :: "r"(mbar), "r"(cnt) : "memory");
}
__device__ __forceinline__ void mbar_expect_tx(uint32_t mbar, uint32_t bytes) {
    asm volatile("mbarrier.arrive.expect_tx.shared::cta.b64 _, [%0], %1;"
                 :: "r"(mbar), "r"(bytes) : "memory");
}
__device__ __forceinline__ void mbar_wait(uint32_t mbar, uint32_t parity) {
    asm volatile(
        "{\n\t"
        ".reg .pred P;\n\t"
        "WAIT_%=: \n\t"
        "mbarrier.try_wait.parity.acquire.cta.shared::cta.b64 P, [%0], %1, 0x989680;\n\t"
        "@P bra.uni DONE_%=;\n\t"
        "bra.uni WAIT_%=;\n\t"
        "DONE_%=: \n\t"
        "}"
        :: "r"(mbar), "r"(parity) : "memory");
}
__device__ __forceinline__ void bulk_copy(uint32_t dst, const void* src,
                                          uint32_t bytes, uint32_t mbar) {
    asm volatile(
        "cp.async.bulk.shared::cta.global.mbarrier::complete_tx::bytes "
        "[%0], [%1], %2, [%3];"
        :: "r"(dst), "l"(src), "r"(bytes), "r"(mbar) : "memory");
}

__device__ __forceinline__ void mma_tf32(
    float acc[4], uint32_t a0, uint32_t a1, uint32_t a2, uint32_t a3,
    uint32_t b0, uint32_t b1)
{
    asm volatile(
        "mma.sync.aligned.m16n8k8.row.col.f32.tf32.tf32.f32 "
        "{%0,%1,%2,%3}, {%4,%5,%6,%7}, {%8,%9}, {%0,%1,%2,%3};\n"
        : "+f"(acc[0]), "+f"(acc[1]), "+f"(acc[2]), "+f"(acc[3])
        : "r"(a0), "r"(a1), "r"(a2), "r"(a3), "r"(b0), "r"(b1));
}

__global__ __launch_bounds__(256) void project_kernel(
    const float* __restrict__ emb,
    const float* __restrict__ Vw)
{
    extern __shared__ float smem[];
    float* sA[2] = { smem, smem + STAGE_ELEMS };
    uint2* sB    = (uint2*)(smem + 2 * STAGE_ELEMS);
    const uint32_t mbar0 = smem_u32(smem + MBAR_OFF);
    const uint32_t mbar1 = mbar0 + 8;

    const int tid  = threadIdx.x;
    const int warp = tid >> 5;
    const int lane = tid & 31;
    const int g4   = lane >> 2;
    const int tg   = lane & 3;

    if (tid == 0) {
        mbar_init(mbar0, 1);
        mbar_init(mbar1, 1);
        asm volatile("fence.proxy.async.shared::cta;" ::: "memory");
    }
    __syncthreads();

    int t = blockIdx.x;
    if (tid == 0 && t < NT_TILES) {
        mbar_expect_tx(mbar0, TILE_BYTES);
        bulk_copy(smem_u32(sA[0]), emb + (size_t)t * TILE_ELEMS, TILE_BYTES, mbar0);
    }

    // Pack B fragment pairs once: sB[(ks*4+nt)*32 + lane] = {bits(Vw[n][k]),
    // bits(Vw[n][k+4])}, n = nt*8 + lane/4, k = ks*8 + lane%4. Raw fp32 bits.
    for (int i = tid; i < B_PAIRS; i += 256) {
        int l  = i & 31;
        int nt = (i >> 5) & 3;
        int ks = i >> 7;
        int k  = ks * 8 + (l & 3);
        int n  = nt * 8 + (l >> 2);
        uint2 v;
        v.x = (k     < DIM) ? __float_as_uint(Vw[n * DIM + k])     : 0u;
        v.y = (k + 4 < DIM) ? __float_as_uint(Vw[n * DIM + k + 4]) : 0u;
        sB[i] = v;
    }
    if (tid < PAD_ELEMS) {
        sA[0][TILE_ELEMS + tid] = 0.0f;
        sA[1][TILE_ELEMS + tid] = 0.0f;
    }
    __syncthreads();

    const int warpRow = warp >> 1;               // 0..3
    const int colHalf = warp & 1;                // 0/1
    const int aRow    = warpRow * 16 + g4;

    int stage = 0;
    uint32_t ph[2] = {0, 0};
    const uint32_t mbars[2] = {mbar0, mbar1};

    for (; t < NT_TILES; t += gridDim.x) {
        int tn = t + gridDim.x;
        if (tid == 0 && tn < NT_TILES) {
            mbar_expect_tx(mbars[stage ^ 1], TILE_BYTES);
            bulk_copy(smem_u32(sA[stage ^ 1]), emb + (size_t)tn * TILE_ELEMS,
                      TILE_BYTES, mbars[stage ^ 1]);
        }

        mbar_wait(mbars[stage], ph[stage]);
        ph[stage] ^= 1;

        const uint32_t* A = (const uint32_t*)sA[stage] + aRow * DIM + tg;
        const uint2*    B = sB + (colHalf * 2) * 32 + lane;

        // 4 independent accumulator chains: {even,odd} k-phase x 2 n-tiles
        float accE0[4] = {0.f, 0.f, 0.f, 0.f};
        float accE1[4] = {0.f, 0.f, 0.f, 0.f};
        float accO0[4] = {0.f, 0.f, 0.f, 0.f};
        float accO1[4] = {0.f, 0.f, 0.f, 0.f};

        #pragma unroll
        for (int ks = 0; ks < KSTEPS; ks += 2) {
            // even phase
            {
                const uint32_t* Ap = A + ks * 8;
                uint32_t a0 = Ap[0], a1 = Ap[8 * DIM], a2 = Ap[4], a3 = Ap[8 * DIM + 4];
                const uint2* Bp = B + ks * 4 * 32;
                uint2 b0 = Bp[0], b1 = Bp[32];
                mma_tf32(accE0, a0, a1, a2, a3, b0.x, b0.y);
                mma_tf32(accE1, a0, a1, a2, a3, b1.x, b1.y);
            }
            // odd phase (independent accumulators)
            {
                const uint32_t* Ap = A + (ks + 1) * 8;
                uint32_t a0 = Ap[0], a1 = Ap[8 * DIM], a2 = Ap[4], a3 = Ap[8 * DIM + 4];
                const uint2* Bp = B + (ks + 1) * 4 * 32;
                uint2 b0 = Bp[0], b1 = Bp[32];
                mma_tf32(accO0, a0, a1, a2, a3, b0.x, b0.y);
                mma_tf32(accO1, a0, a1, a2, a3, b1.x, b1.y);
            }
        }

        // combine phases and store 16x16 per warp (float2 stores)
        int rbase = t * TILE_R + warpRow * 16;
        {
            int col = colHalf * 16 + tg * 2;
            int r0  = rbase + g4;
            *(float2*)&g_E2[(size_t)r0 * HID + col] =
                make_float2(accE0[0] + accO0[0], accE0[1] + accO0[1]);
            *(float2*)&g_E2[(size_t)(r0 + 8) * HID + col] =
                make_float2(accE0[2] + accO0[2], accE0[3] + accO0[3]);
            col += 8;
            *(float2*)&g_E2[(size_t)r0 * HID + col] =
                make_float2(accE1[0] + accO1[0], accE1[1] + accO1[1]);
            *(float2*)&g_E2[(size_t)(r0 + 8) * HID + col] =
                make_float2(accE1[2] + accO1[2], accE1[3] + accO1[3]);
        }

        __syncthreads();   // all warps done with this stage before refill
        stage ^= 1;
    }
}

// ---------------------------------------------------------------------------
// Pass B: gather E2 rows, mean-pool, relu MLP head -> logits.
// One warp per batch row; lane = hidden unit. 128B coalesced gathers.
// ---------------------------------------------------------------------------
__global__ __launch_bounds__(256) void gather_kernel(
    const int*   __restrict__ tokens,
    const float* __restrict__ Vb,
    const float* __restrict__ Ww,
    const float* __restrict__ Wb,
    float*       __restrict__ out)
{
    const int b    = blockIdx.x * 8 + (threadIdx.x >> 5);
    const int lane = threadIdx.x & 31;

    int t0 = tokens[b * SEQ + lane];
    int t1 = (lane < SEQ - 32) ? tokens[b * SEQ + 32 + lane] : 0;

    float acc = 0.f;
    #pragma unroll
    for (int k = 0; k < SEQ; k++) {
        int tok = (k < 32) ? __shfl_sync(0xffffffffu, t0, k)
                           : __shfl_sync(0xffffffffu, t1, k - 32);
        acc += __ldg(&g_E2[(size_t)tok * HID + lane]);
    }

    float h  = fmaxf(acc * (1.0f / (float)SEQ) + Vb[lane], 0.f);
    float p0 = h * Ww[lane];          // Ww[0][lane]
    float p1 = h * Ww[HID + lane];    // Ww[1][lane]
    #pragma unroll
    for (int off = 16; off; off >>= 1) {
        p0 += __shfl_xor_sync(0xffffffffu, p0, off);
        p1 += __shfl_xor_sync(0xffffffffu, p1, off);
    }
    if (lane == 0) {
        out[b * OUTC + 0] = p0 + Wb[0];
        out[b * OUTC + 1] = p1 + Wb[1];
    }
}

// ---------------------------------------------------------------------------
// Pass C: column-wise logsumexp over the batch axis + in-place subtract.
// Single CTA (fused lse + apply).
// ---------------------------------------------------------------------------
__global__ __launch_bounds__(1024) void lse_apply_kernel(float* __restrict__ logits)
{
    __shared__ float2 red[1024];
    const int tid = threadIdx.x;

    float m0 = -1e30f, m1 = -1e30f;
    for (int r = tid; r < BATCH; r += 1024) {
        float2 v = reinterpret_cast<const float2*>(logits)[r];
        m0 = fmaxf(m0, v.x);
        m1 = fmaxf(m1, v.y);
    }
    red[tid] = make_float2(m0, m1);
    __syncthreads();
    for (int s = 512; s; s >>= 1) {
        if (tid < s) {
            red[tid].x = fmaxf(red[tid].x, red[tid + s].x);
            red[tid].y = fmaxf(red[tid].y, red[tid + s].y);
        }
        __syncthreads();
    }
    m0 = red[0].x; m1 = red[0].y;
    __syncthreads();

    float s0 = 0.f, s1 = 0.f;
    for (int r = tid; r < BATCH; r += 1024) {
        float2 v = reinterpret_cast<const float2*>(logits)[r];
        s0 += expf(v.x - m0);
        s1 += expf(v.y - m1);
    }
    red[tid] = make_float2(s0, s1);
    __syncthreads();
    for (int s = 512; s; s >>= 1) {
        if (tid < s) {
            red[tid].x += red[tid + s].x;
            red[tid].y += red[tid + s].y;
        }
        __syncthreads();
    }
    __syncthreads();
    const float l0 = m0 + logf(red[0].x);
    const float l1 = m1 + logf(red[0].y);

    for (int r = tid; r < BATCH; r += 1024) {
        float2 v = reinterpret_cast<float2*>(logits)[r];
        v.x -= l0;
        v.y -= l1;
        reinterpret_cast<float2*>(logits)[r] = v;
    }
}

extern "C" void kernel_launch(void* const* d_in, const int* in_sizes, int n_in,
                              void* d_out, int out_size)
{
    const int*   tokens = (const int*)  d_in[0];
    const float* emb    = (const float*)d_in[1];
    const float* Vw     = (const float*)d_in[2];
    const float* Vb     = (const float*)d_in[3];
    const float* Ww     = (const float*)d_in[4];
    const float* Wb     = (const float*)d_in[5];
    float* out = (float*)d_out;

    cudaFuncSetAttribute(project_kernel,
                         cudaFuncAttributeMaxDynamicSharedMemorySize, SMEM_BYTES);

    project_kernel<<<148, 256, SMEM_BYTES>>>(emb, Vw);
    gather_kernel<<<BATCH / 8, 256>>>(tokens, Vb, Ww, Wb, out);
    lse_apply_kernel<<<1, 1024>>>(out);
}

// round 7
// speedup vs baseline: 1.2721x; 1.0199x over previous
#include <cuda_runtime.h>
#include <math.h>
#include <stdint.h>

#define BATCH 16384
#define SEQ   50
#define DIM   300
#define HID   32
#define OUTC  2
#define VOCAB 400000

// allocation-free scratch
__device__ float g_E2[(size_t)VOCAB * HID];   // 51.2 MB projected table

// ---------------------------------------------------------------------------
// Pass A: E2[v][j] = sum_d emb[v][d] * Vw[j][d]   (400000x300 @ 300x32)
// tf32 mma.sync m16n8k8, raw fp32 bits fed as tf32 (RZ truncation, no cvt).
// 148 persistent CTAs x 256 threads, split into TWO independent 4-warp teams
// per CTA. Each team owns its own 32-row tile stream, its own 2 double-
// buffered stages + mbarriers, and team-local bar.sync -- two decoupled
// pipelines per SM, so one team's wait/barrier tail is covered by the other
// team's compute. Per warp: 16 rows x 16 cols, 4 independent MMA chains
// (even/odd K phases x 2 n-tiles), k-loop fully unrolled.
// ---------------------------------------------------------------------------
#define TILE_R     32
#define KSTEPS     38                        // ceil(300/8); k>=300 hits zero B
#define NT32       (VOCAB / TILE_R)          // 12500 32-row tiles
#define VGRID      296                       // 148 CTAs x 2 teams
#define TILE_ELEMS (TILE_R * DIM)            // 9600 floats
#define TILE_BYTES (TILE_ELEMS * 4)          // 38400 B
#define B_PAIRS    (KSTEPS * 4 * 32)         // 4864 uint2 = 38912 B
// layout: stage0..stage3 | sB(uint2) | 4 mbarriers
#define MBAR_OFF   (4 * TILE_ELEMS + 2 * B_PAIRS)   // float idx, 16B aligned
#define SMEM_BYTES ((MBAR_OFF + 8) * 4)             // + 32 B for 4 mbarriers

__device__ __forceinline__ uint32_t smem_u32(const void* p) {
    return (uint32_t)__cvta_generic_to_shared(p);
}
__device__ __forceinline__ void mbar_init(uint32_t mbar, uint32_t cnt) {
    asm volatile("mbarrier.init.shared::cta.b64 [%0], %1;" :: "r"(mbar), "r"(cnt) : "memory");
}
__device__ __forceinline__ void mbar_expect_tx(uint32_t mbar, uint32_t bytes) {
    asm volatile("mbarrier.arrive.expect_tx.shared::cta.b64 _, [%0], %1;"
                 :: "r"(mbar), "r"(bytes) : "memory");
}
__device__ __forceinline__ void mbar_wait(uint32_t mbar, uint32_t parity) {
    asm volatile(
        "{\n\t"
        ".reg .pred P;\n\t"
        "WAIT_%=: \n\t"
        "mbarrier.try_wait.parity.acquire.cta.shared::cta.b64 P, [%0], %1, 0x989680;\n\t"
        "@P bra.uni DONE_%=;\n\t"
        "bra.uni WAIT_%=;\n\t"
        "DONE_%=: \n\t"
        "}"
        :: "r"(mbar), "r"(parity) : "memory");
}
__device__ __forceinline__ void bulk_copy(uint32_t dst, const void* src,
                                          uint32_t bytes, uint32_t mbar) {
    asm volatile(
        "cp.async.bulk.shared::cta.global.mbarrier::complete_tx::bytes "
        "[%0], [%1], %2, [%3];"
        :: "r"(dst), "l"(src), "r"(bytes), "r"(mbar) : "memory");
}
__device__ __forceinline__ void mma_tf32(
    float acc[4], uint32_t a0, uint32_t a1, uint32_t a2, uint32_t a3,
    uint32_t b0, uint32_t b1)
{
    asm volatile(
        "mma.sync.aligned.m16n8k8.row.col.f32.tf32.tf32.f32 "
        "{%0,%1,%2,%3}, {%4,%5,%6,%7}, {%8,%9}, {%0,%1,%2,%3};\n"
        : "+f"(acc[0]), "+f"(acc[1]), "+f"(acc[2]), "+f"(acc[3])
        : "r"(a0), "r"(a1), "r"(a2), "r"(a3), "r"(b0), "r"(b1));
}

__global__ __launch_bounds__(256) void project_kernel(
    const float* __restrict__ emb,
    const float* __restrict__ Vw)
{
    extern __shared__ float smem[];
    uint2* sB = (uint2*)(smem + 4 * TILE_ELEMS);
    const uint32_t mbarBase = smem_u32(smem + MBAR_OFF);

    const int tid  = threadIdx.x;
    const int warp = tid >> 5;
    const int lane = tid & 31;
    const int g4   = lane >> 2;
    const int tg   = lane & 3;

    const int team    = warp >> 2;            // 0 or 1
    const int wInTeam = warp & 3;
    const int teamRow = wInTeam >> 1;         // 0..1
    const int colHalf = wInTeam & 1;          // 0..1
    const int aRow    = teamRow * 16 + g4;

    // team-local resources
    float* stg[2] = { smem + (2 * team)     * TILE_ELEMS,
                      smem + (2 * team + 1) * TILE_ELEMS };
    const uint32_t mb[2] = { mbarBase + (2 * team) * 8,
                             mbarBase + (2 * team + 1) * 8 };

    if (tid == 0) {
        #pragma unroll
        for (int i = 0; i < 4; i++) mbar_init(mbarBase + i * 8, 1);
        asm volatile("fence.proxy.async.shared::cta;" ::: "memory");
    }
    __syncthreads();

    const int vid = blockIdx.x * 2 + team;    // virtual stream id, 0..295

    // team's elected thread kicks off first tile load
    const bool elected = ((tid & 127) == 0);
    if (elected && vid < NT32) {
        mbar_expect_tx(mb[0], TILE_BYTES);
        bulk_copy(smem_u32(stg[0]), emb + (size_t)vid * TILE_ELEMS, TILE_BYTES, mb[0]);
    }

    // Pack B fragment pairs once (whole CTA): sB[(ks*4+nt)*32 + lane] =
    // {bits(Vw[n][k]), bits(Vw[n][k+4])}, n = nt*8+lane/4, k = ks*8+lane%4.
    for (int i = tid; i < B_PAIRS; i += 256) {
        int l  = i & 31;
        int nt = (i >> 5) & 3;
        int ks = i >> 7;
        int k  = ks * 8 + (l & 3);
        int n  = nt * 8 + (l >> 2);
        uint2 v;
        v.x = (k     < DIM) ? __float_as_uint(Vw[n * DIM + k])     : 0u;
        v.y = (k + 4 < DIM) ? __float_as_uint(Vw[n * DIM + k + 4]) : 0u;
        sB[i] = v;
    }
    __syncthreads();   // sB visible to both teams; teams decouple from here on

    int stage = 0;
    uint32_t ph[2] = {0, 0};

    for (int t = vid; t < NT32; t += VGRID) {
        int tn = t + VGRID;
        // stage^1 was consumed before this team's previous bar.sync
        if (elected && tn < NT32) {
            mbar_expect_tx(mb[stage ^ 1], TILE_BYTES);
            bulk_copy(smem_u32(stg[stage ^ 1]), emb + (size_t)tn * TILE_ELEMS,
                      TILE_BYTES, mb[stage ^ 1]);
        }

        mbar_wait(mb[stage], ph[stage]);
        ph[stage] ^= 1;

        const uint32_t* A = (const uint32_t*)stg[stage] + aRow * DIM + tg;
        const uint2*    B = sB + (colHalf * 2) * 32 + lane;

        // 4 independent accumulator chains: {even,odd} k-phase x 2 n-tiles
        float accE0[4] = {0.f, 0.f, 0.f, 0.f};
        float accE1[4] = {0.f, 0.f, 0.f, 0.f};
        float accO0[4] = {0.f, 0.f, 0.f, 0.f};
        float accO1[4] = {0.f, 0.f, 0.f, 0.f};

        #pragma unroll
        for (int ks = 0; ks < KSTEPS; ks += 2) {
            {
                const uint32_t* Ap = A + ks * 8;
                uint32_t a0 = Ap[0], a1 = Ap[8 * DIM], a2 = Ap[4], a3 = Ap[8 * DIM + 4];
                const uint2* Bp = B + ks * 4 * 32;
                uint2 b0 = Bp[0], b1 = Bp[32];
                mma_tf32(accE0, a0, a1, a2, a3, b0.x, b0.y);
                mma_tf32(accE1, a0, a1, a2, a3, b1.x, b1.y);
            }
            {
                const uint32_t* Ap = A + (ks + 1) * 8;
                uint32_t a0 = Ap[0], a1 = Ap[8 * DIM], a2 = Ap[4], a3 = Ap[8 * DIM + 4];
                const uint2* Bp = B + (ks + 1) * 4 * 32;
                uint2 b0 = Bp[0], b1 = Bp[32];
                mma_tf32(accO0, a0, a1, a2, a3, b0.x, b0.y);
                mma_tf32(accO1, a0, a1, a2, a3, b1.x, b1.y);
            }
        }
        // (ks tail reads spill <=8 floats into the adjacent stage/sB region:
        //  always finite float bits, multiplied by B=0 -> contributes 0.)

        // combine phases and store 16x16 per warp (float2 stores)
        int rbase = t * TILE_R + teamRow * 16;
        {
            int col = colHalf * 16 + tg * 2;
            int r0  = rbase + g4;
            *(float2*)&g_E2[(size_t)r0 * HID + col] =
                make_float2(accE0[0] + accO0[0], accE0[1] + accO0[1]);
            *(float2*)&g_E2[(size_t)(r0 + 8) * HID + col] =
                make_float2(accE0[2] + accO0[2], accE0[3] + accO0[3]);
            col += 8;
            *(float2*)&g_E2[(size_t)r0 * HID + col] =
                make_float2(accE1[0] + accO1[0], accE1[1] + accO1[1]);
            *(float2*)&g_E2[(size_t)(r0 + 8) * HID + col] =
                make_float2(accE1[2] + accO1[2], accE1[3] + accO1[3]);
        }

        // team-local barrier: all 4 warps of this team done with this stage
        asm volatile("bar.sync %0, 128;" :: "r"(team + 1) : "memory");
        stage ^= 1;
    }
}

// ---------------------------------------------------------------------------
// Pass B: gather E2 rows, mean-pool, relu MLP head -> logits.
// One warp per batch row; lane = hidden unit. 128B coalesced gathers.
// ---------------------------------------------------------------------------
__global__ __launch_bounds__(256) void gather_kernel(
    const int*   __restrict__ tokens,
    const float* __restrict__ Vb,
    const float* __restrict__ Ww,
    const float* __restrict__ Wb,
    float*       __restrict__ out)
{
    const int b    = blockIdx.x * 8 + (threadIdx.x >> 5);
    const int lane = threadIdx.x & 31;

    int t0 = tokens[b * SEQ + lane];
    int t1 = (lane < SEQ - 32) ? tokens[b * SEQ + 32 + lane] : 0;

    float acc = 0.f;
    #pragma unroll
    for (int k = 0; k < SEQ; k++) {
        int tok = (k < 32) ? __shfl_sync(0xffffffffu, t0, k)
                           : __shfl_sync(0xffffffffu, t1, k - 32);
        acc += __ldg(&g_E2[(size_t)tok * HID + lane]);
    }

    float h  = fmaxf(acc * (1.0f / (float)SEQ) + Vb[lane], 0.f);
    float p0 = h * Ww[lane];          // Ww[0][lane]
    float p1 = h * Ww[HID + lane];    // Ww[1][lane]
    #pragma unroll
    for (int off = 16; off; off >>= 1) {
        p0 += __shfl_xor_sync(0xffffffffu, p0, off);
        p1 += __shfl_xor_sync(0xffffffffu, p1, off);
    }
    if (lane == 0) {
        out[b * OUTC + 0] = p0 + Wb[0];
        out[b * OUTC + 1] = p1 + Wb[1];
    }
}

// ---------------------------------------------------------------------------
// Pass C: column-wise logsumexp over the batch axis + in-place subtract.
// Single CTA (fused lse + apply).
// ---------------------------------------------------------------------------
__global__ __launch_bounds__(1024) void lse_apply_kernel(float* __restrict__ logits)
{
    __shared__ float2 red[1024];
    const int tid = threadIdx.x;

    float m0 = -1e30f, m1 = -1e30f;
    for (int r = tid; r < BATCH; r += 1024) {
        float2 v = reinterpret_cast<const float2*>(logits)[r];
        m0 = fmaxf(m0, v.x);
        m1 = fmaxf(m1, v.y);
    }
    red[tid] = make_float2(m0, m1);
    __syncthreads();
    for (int s = 512; s; s >>= 1) {
        if (tid < s) {
            red[tid].x = fmaxf(red[tid].x, red[tid + s].x);
            red[tid].y = fmaxf(red[tid].y, red[tid + s].y);
        }
        __syncthreads();
    }
    m0 = red[0].x; m1 = red[0].y;
    __syncthreads();

    float s0 = 0.f, s1 = 0.f;
    for (int r = tid; r < BATCH; r += 1024) {
        float2 v = reinterpret_cast<const float2*>(logits)[r];
        s0 += expf(v.x - m0);
        s1 += expf(v.y - m1);
    }
    red[tid] = make_float2(s0, s1);
    __syncthreads();
    for (int s = 512; s; s >>= 1) {
        if (tid < s) {
            red[tid].x += red[tid + s].x;
            red[tid].y += red[tid + s].y;
        }
        __syncthreads();
    }
    __syncthreads();
    const float l0 = m0 + logf(red[0].x);
    const float l1 = m1 + logf(red[0].y);

    for (int r = tid; r < BATCH; r += 1024) {
        float2 v = reinterpret_cast<float2*>(logits)[r];
        v.x -= l0;
        v.y -= l1;
        reinterpret_cast<float2*>(logits)[r] = v;
    }
}

extern "C" void kernel_launch(void* const* d_in, const int* in_sizes, int n_in,
                              void* d_out, int out_size)
{
    const int*   tokens = (const int*)  d_in[0];
    const float* emb    = (const float*)d_in[1];
    const float* Vw     = (const float*)d_in[2];
    const float* Vb     = (const float*)d_in[3];
    const float* Ww     = (const float*)d_in[4];
    const float* Wb     = (const float*)d_in[5];
    float* out = (float*)d_out;

    cudaFuncSetAttribute(project_kernel,
                         cudaFuncAttributeMaxDynamicSharedMemorySize, SMEM_BYTES);

    project_kernel<<<148, 256, SMEM_BYTES>>>(emb, Vw);
    gather_kernel<<<BATCH / 8, 256>>>(tokens, Vb, Ww, Wb, out);
    lse_apply_kernel<<<1, 1024>>>(out);
}

// round 8
// speedup vs baseline: 1.3384x; 1.0521x over previous
#include <cuda_runtime.h>
#include <math.h>
#include <stdint.h>

#define BATCH 16384
#define SEQ   50
#define DIM   300
#define HID   32
#define OUTC  2
#define VOCAB 400000

// allocation-free scratch
__device__ float g_E2[(size_t)VOCAB * HID];   // 51.2 MB projected table

// ---------------------------------------------------------------------------
// Pass A: E2[v][j] = sum_d emb[v][d] * Vw[j][d]   (400000x300 @ 300x32)
// tf32 mma.sync m16n8k8, raw fp32 bits fed as tf32 (RZ truncation).
// 148 persistent CTAs x 256 threads, two independent 4-warp teams per CTA,
// each with its own 32-row tile stream, double-buffered TMA bulk copies and
// team-local bar.sync.
// KEY CHANGE (R8): B fragments are tile-invariant -> each warp loads its 152
// B registers (38 ksteps x 2 n-tiles x uint2) ONCE and never touches sB in
// the mainloop. Mainloop smem traffic = 4x LDS.32 (A) per kstep only, which
// drops LDS bytes/SM below the DRAM budget -> HBM becomes the limiter.
// ---------------------------------------------------------------------------
#define TILE_R     32
#define KSTEPS     38                        // ceil(300/8); k>=300 hits zero B
#define NT32       (VOCAB / TILE_R)          // 12500 32-row tiles
#define VGRID      296                       // 148 CTAs x 2 teams
#define TILE_ELEMS (TILE_R * DIM)            // 9600 floats
#define TILE_BYTES (TILE_ELEMS * 4)          // 38400 B
#define B_PAIRS    (KSTEPS * 4 * 32)         // 4864 uint2 = 38912 B
// layout: stage0..stage3 | sB(uint2) | 4 mbarriers
#define MBAR_OFF   (4 * TILE_ELEMS + 2 * B_PAIRS)   // float idx, 16B aligned
#define SMEM_BYTES ((MBAR_OFF + 8) * 4)             // + 32 B for 4 mbarriers

__device__ __forceinline__ uint32_t smem_u32(const void* p) {
    return (uint32_t)__cvta_generic_to_shared(p);
}
__device__ __forceinline__ void mbar_init(uint32_t mbar, uint32_t cnt) {
    asm volatile("mbarrier.init.shared::cta.b64 [%0], %1;" :: "r"(mbar), "r"(cnt) : "memory");
}
__device__ __forceinline__ void mbar_expect_tx(uint32_t mbar, uint32_t bytes) {
    asm volatile("mbarrier.arrive.expect_tx.shared::cta.b64 _, [%0], %1;"
                 :: "r"(mbar), "r"(bytes) : "memory");
}
__device__ __forceinline__ void mbar_wait(uint32_t mbar, uint32_t parity) {
    asm volatile(
        "{\n\t"
        ".reg .pred P;\n\t"
        "WAIT_%=: \n\t"
        "mbarrier.try_wait.parity.acquire.cta.shared::cta.b64 P, [%0], %1, 0x989680;\n\t"
        "@P bra.uni DONE_%=;\n\t"
        "bra.uni WAIT_%=;\n\t"
        "DONE_%=: \n\t"
        "}"
        :: "r"(mbar), "r"(parity) : "memory");
}
__device__ __forceinline__ void bulk_copy(uint32_t dst, const void* src,
                                          uint32_t bytes, uint32_t mbar) {
    asm volatile(
        "cp.async.bulk.shared::cta.global.mbarrier::complete_tx::bytes "
        "[%0], [%1], %2, [%3];"
        :: "r"(dst), "l"(src), "r"(bytes), "r"(mbar) : "memory");
}
__device__ __forceinline__ void mma_tf32(
    float acc[4], uint32_t a0, uint32_t a1, uint32_t a2, uint32_t a3,
    uint32_t b0, uint32_t b1)
{
    asm volatile(
        "mma.sync.aligned.m16n8k8.row.col.f32.tf32.tf32.f32 "
        "{%0,%1,%2,%3}, {%4,%5,%6,%7}, {%8,%9}, {%0,%1,%2,%3};\n"
        : "+f"(acc[0]), "+f"(acc[1]), "+f"(acc[2]), "+f"(acc[3])
        : "r"(a0), "r"(a1), "r"(a2), "r"(a3), "r"(b0), "r"(b1));
}

__global__ __launch_bounds__(256) void project_kernel(
    const float* __restrict__ emb,
    const float* __restrict__ Vw)
{
    extern __shared__ float smem[];
    uint2* sB = (uint2*)(smem + 4 * TILE_ELEMS);
    const uint32_t mbarBase = smem_u32(smem + MBAR_OFF);

    const int tid  = threadIdx.x;
    const int warp = tid >> 5;
    const int lane = tid & 31;
    const int g4   = lane >> 2;
    const int tg   = lane & 3;

    const int team    = warp >> 2;            // 0 or 1
    const int wInTeam = warp & 3;
    const int teamRow = wInTeam >> 1;         // 0..1
    const int colHalf = wInTeam & 1;          // 0..1
    const int aRow    = teamRow * 16 + g4;

    // team-local resources
    float* stg[2] = { smem + (2 * team)     * TILE_ELEMS,
                      smem + (2 * team + 1) * TILE_ELEMS };
    const uint32_t mb[2] = { mbarBase + (2 * team) * 8,
                             mbarBase + (2 * team + 1) * 8 };

    if (tid == 0) {
        #pragma unroll
        for (int i = 0; i < 4; i++) mbar_init(mbarBase + i * 8, 1);
        asm volatile("fence.proxy.async.shared::cta;" ::: "memory");
    }
    __syncthreads();

    const int vid = blockIdx.x * 2 + team;    // virtual stream id, 0..295

    // team's elected thread kicks off first tile load
    const bool elected = ((tid & 127) == 0);
    if (elected && vid < NT32) {
        mbar_expect_tx(mb[0], TILE_BYTES);
        bulk_copy(smem_u32(stg[0]), emb + (size_t)vid * TILE_ELEMS, TILE_BYTES, mb[0]);
    }

    // Pack B fragment pairs once (whole CTA): sB[(ks*4+nt)*32 + lane] =
    // {bits(Vw[n][k]), bits(Vw[n][k+4])}, n = nt*8+lane/4, k = ks*8+lane%4.
    for (int i = tid; i < B_PAIRS; i += 256) {
        int l  = i & 31;
        int nt = (i >> 5) & 3;
        int ks = i >> 7;
        int k  = ks * 8 + (l & 3);
        int n  = nt * 8 + (l >> 2);
        uint2 v;
        v.x = (k     < DIM) ? __float_as_uint(Vw[n * DIM + k])     : 0u;
        v.y = (k + 4 < DIM) ? __float_as_uint(Vw[n * DIM + k + 4]) : 0u;
        sB[i] = v;
    }
    __syncthreads();

    // ---- hoist this warp's B fragments into registers, permanently ----
    // bregX[ks] = sB[(ks*4 + colHalf*2 + X)*32 + lane]; never LDS B again.
    uint2 breg0[KSTEPS], breg1[KSTEPS];
    {
        const uint2* B = sB + (colHalf * 2) * 32 + lane;
        #pragma unroll
        for (int ks = 0; ks < KSTEPS; ks++) {
            breg0[ks] = B[ks * 4 * 32];
            breg1[ks] = B[ks * 4 * 32 + 32];
        }
    }

    int stage = 0;
    uint32_t ph[2] = {0, 0};

    for (int t = vid; t < NT32; t += VGRID) {
        int tn = t + VGRID;
        // stage^1 was consumed before this team's previous bar.sync
        if (elected && tn < NT32) {
            mbar_expect_tx(mb[stage ^ 1], TILE_BYTES);
            bulk_copy(smem_u32(stg[stage ^ 1]), emb + (size_t)tn * TILE_ELEMS,
                      TILE_BYTES, mb[stage ^ 1]);
        }

        mbar_wait(mb[stage], ph[stage]);
        ph[stage] ^= 1;

        const uint32_t* A = (const uint32_t*)stg[stage] + aRow * DIM + tg;

        // 4 independent accumulator chains: {even,odd} k-phase x 2 n-tiles
        float accE0[4] = {0.f, 0.f, 0.f, 0.f};
        float accE1[4] = {0.f, 0.f, 0.f, 0.f};
        float accO0[4] = {0.f, 0.f, 0.f, 0.f};
        float accO1[4] = {0.f, 0.f, 0.f, 0.f};

        #pragma unroll
        for (int ks = 0; ks < KSTEPS; ks += 2) {
            {
                const uint32_t* Ap = A + ks * 8;
                uint32_t a0 = Ap[0], a1 = Ap[8 * DIM], a2 = Ap[4], a3 = Ap[8 * DIM + 4];
                mma_tf32(accE0, a0, a1, a2, a3, breg0[ks].x, breg0[ks].y);
                mma_tf32(accE1, a0, a1, a2, a3, breg1[ks].x, breg1[ks].y);
            }
            {
                const uint32_t* Ap = A + (ks + 1) * 8;
                uint32_t a0 = Ap[0], a1 = Ap[8 * DIM], a2 = Ap[4], a3 = Ap[8 * DIM + 4];
                mma_tf32(accO0, a0, a1, a2, a3, breg0[ks + 1].x, breg0[ks + 1].y);
                mma_tf32(accO1, a0, a1, a2, a3, breg1[ks + 1].x, breg1[ks + 1].y);
            }
        }
        // (ks tail reads spill <=8 floats into the adjacent stage/sB region:
        //  always finite float bits, multiplied by B=0 -> contributes 0.)

        // combine phases and store 16x16 per warp (float2 stores)
        int rbase = t * TILE_R + teamRow * 16;
        {
            int col = colHalf * 16 + tg * 2;
            int r0  = rbase + g4;
            *(float2*)&g_E2[(size_t)r0 * HID + col] =
                make_float2(accE0[0] + accO0[0], accE0[1] + accO0[1]);
            *(float2*)&g_E2[(size_t)(r0 + 8) * HID + col] =
                make_float2(accE0[2] + accO0[2], accE0[3] + accO0[3]);
            col += 8;
            *(float2*)&g_E2[(size_t)r0 * HID + col] =
                make_float2(accE1[0] + accO1[0], accE1[1] + accO1[1]);
            *(float2*)&g_E2[(size_t)(r0 + 8) * HID + col] =
                make_float2(accE1[2] + accO1[2], accE1[3] + accO1[3]);
        }

        // team-local barrier: all 4 warps of this team done with this stage
        asm volatile("bar.sync %0, 128;" :: "r"(team + 1) : "memory");
        stage ^= 1;
    }
}

// ---------------------------------------------------------------------------
// Pass B: gather E2 rows, mean-pool, relu MLP head -> logits.
// One warp per batch row; lane = hidden unit. 128B coalesced gathers.
// ---------------------------------------------------------------------------
__global__ __launch_bounds__(256) void gather_kernel(
    const int*   __restrict__ tokens,
    const float* __restrict__ Vb,
    const float* __restrict__ Ww,
    const float* __restrict__ Wb,
    float*       __restrict__ out)
{
    const int b    = blockIdx.x * 8 + (threadIdx.x >> 5);
    const int lane = threadIdx.x & 31;

    int t0 = tokens[b * SEQ + lane];
    int t1 = (lane < SEQ - 32) ? tokens[b * SEQ + 32 + lane] : 0;

    float acc = 0.f;
    #pragma unroll
    for (int k = 0; k < SEQ; k++) {
        int tok = (k < 32) ? __shfl_sync(0xffffffffu, t0, k)
                           : __shfl_sync(0xffffffffu, t1, k - 32);
        acc += __ldg(&g_E2[(size_t)tok * HID + lane]);
    }

    float h  = fmaxf(acc * (1.0f / (float)SEQ) + Vb[lane], 0.f);
    float p0 = h * Ww[lane];          // Ww[0][lane]
    float p1 = h * Ww[HID + lane];    // Ww[1][lane]
    #pragma unroll
    for (int off = 16; off; off >>= 1) {
        p0 += __shfl_xor_sync(0xffffffffu, p0, off);
        p1 += __shfl_xor_sync(0xffffffffu, p1, off);
    }
    if (lane == 0) {
        out[b * OUTC + 0] = p0 + Wb[0];
        out[b * OUTC + 1] = p1 + Wb[1];
    }
}

// ---------------------------------------------------------------------------
// Pass C: column-wise logsumexp over the batch axis + in-place subtract.
// Single CTA (fused lse + apply).
// ---------------------------------------------------------------------------
__global__ __launch_bounds__(1024) void lse_apply_kernel(float* __restrict__ logits)
{
    __shared__ float2 red[1024];
    const int tid = threadIdx.x;

    float m0 = -1e30f, m1 = -1e30f;
    for (int r = tid; r < BATCH; r += 1024) {
        float2 v = reinterpret_cast<const float2*>(logits)[r];
        m0 = fmaxf(m0, v.x);
        m1 = fmaxf(m1, v.y);
    }
    red[tid] = make_float2(m0, m1);
    __syncthreads();
    for (int s = 512; s; s >>= 1) {
        if (tid < s) {
            red[tid].x = fmaxf(red[tid].x, red[tid + s].x);
            red[tid].y = fmaxf(red[tid].y, red[tid + s].y);
        }
        __syncthreads();
    }
    m0 = red[0].x; m1 = red[0].y;
    __syncthreads();

    float s0 = 0.f, s1 = 0.f;
    for (int r = tid; r < BATCH; r += 1024) {
        float2 v = reinterpret_cast<const float2*>(logits)[r];
        s0 += expf(v.x - m0);
        s1 += expf(v.y - m1);
    }
    red[tid] = make_float2(s0, s1);
    __syncthreads();
    for (int s = 512; s; s >>= 1) {
        if (tid < s) {
            red[tid].x += red[tid + s].x;
            red[tid].y += red[tid + s].y;
        }
        __syncthreads();
    }
    __syncthreads();
    const float l0 = m0 + logf(red[0].x);
    const float l1 = m1 + logf(red[0].y);

    for (int r = tid; r < BATCH; r += 1024) {
        float2 v = reinterpret_cast<float2*>(logits)[r];
        v.x -= l0;
        v.y -= l1;
        reinterpret_cast<float2*>(logits)[r] = v;
    }
}

extern "C" void kernel_launch(void* const* d_in, const int* in_sizes, int n_in,
                              void* d_out, int out_size)
{
    const int*   tokens = (const int*)  d_in[0];
    const float* emb    = (const float*)d_in[1];
    const float* Vw     = (const float*)d_in[2];
    const float* Vb     = (const float*)d_in[3];
    const float* Ww     = (const float*)d_in[4];
    const float* Wb     = (const float*)d_in[5];
    float* out = (float*)d_out;

    cudaFuncSetAttribute(project_kernel,
                         cudaFuncAttributeMaxDynamicSharedMemorySize, SMEM_BYTES);

    project_kernel<<<148, 256, SMEM_BYTES>>>(emb, Vw);
    gather_kernel<<<BATCH / 8, 256>>>(tokens, Vb, Ww, Wb, out);
    lse_apply_kernel<<<1, 1024>>>(out);
}

// round 9
// speedup vs baseline: 1.4678x; 1.0966x over previous
#include <cuda_runtime.h>
#include <math.h>
#include <stdint.h>

#define BATCH 16384
#define SEQ   50
#define DIM   300
#define HID   32
#define OUTC  2
#define VOCAB 400000

// allocation-free scratch
__device__ float g_E2[(size_t)VOCAB * HID];   // 51.2 MB projected table

// ---------------------------------------------------------------------------
// Pass A: E2[v][j] = sum_d emb[v][d] * Vw[j][d]   (400000x300 @ 300x32)
// tf32 mma.sync m16n8k8, raw fp32 bits as tf32 (RZ truncation).
// R9: single 5-stage ring per CTA (prefetch depth 5, one cp.async.bulk per
// stage), 148 persistent CTAs x 256 threads, 32-row tiles. B fragments are
// loaded ONCE per warp straight from gmem into 76 registers (sB eliminated;
// its smem pays for pipeline depth). Per warp: 16 rows x 8 cols, even/odd-K
// accumulator chains, k-loop fully unrolled. Main loop unrolled by 5 so slot
// ids / parities are compile-time.
// ---------------------------------------------------------------------------
#define TILE_R     32
#define KSTEPS     38                        // ceil(300/8); k>=300 -> B=0
#define NT32       (VOCAB / TILE_R)          // 12500 tiles
#define GRID       148
#define NSTAGE     5
#define TILE_ELEMS (TILE_R * DIM)            // 9600 floats
#define TILE_BYTES (TILE_ELEMS * 4)          // 38400 B
#define PAD_ELEMS  16                        // zeroed pad after stage 4
// layout: stage0..stage4 | pad | 5 mbarriers
#define MBAR_OFF   (NSTAGE * TILE_ELEMS + PAD_ELEMS)   // float idx, 16B aligned
#define SMEM_BYTES ((MBAR_OFF + 10) * 4)               // + 40 B for 5 mbarriers

__device__ __forceinline__ uint32_t smem_u32(const void* p) {
    return (uint32_t)__cvta_generic_to_shared(p);
}
__device__ __forceinline__ void mbar_init(uint32_t mbar, uint32_t cnt) {
    asm volatile("mbarrier.init.shared::cta.b64 [%0], %1;" :: "r"(mbar), "r"(cnt) : "memory");
}
__device__ __forceinline__ void mbar_expect_tx(uint32_t mbar, uint32_t bytes) {
    asm volatile("mbarrier.arrive.expect_tx.shared::cta.b64 _, [%0], %1;"
                 :: "r"(mbar), "r"(bytes) : "memory");
}
__device__ __forceinline__ void mbar_wait(uint32_t mbar, uint32_t parity) {
    asm volatile(
        "{\n\t"
        ".reg .pred P;\n\t"
        "WAIT_%=: \n\t"
        "mbarrier.try_wait.parity.acquire.cta.shared::cta.b64 P, [%0], %1, 0x989680;\n\t"
        "@P bra.uni DONE_%=;\n\t"
        "bra.uni WAIT_%=;\n\t"
        "DONE_%=: \n\t"
        "}"
        :: "r"(mbar), "r"(parity) : "memory");
}
__device__ __forceinline__ void bulk_copy(uint32_t dst, const void* src,
                                          uint32_t bytes, uint32_t mbar) {
    asm volatile(
        "cp.async.bulk.shared::cta.global.mbarrier::complete_tx::bytes "
        "[%0], [%1], %2, [%3];"
        :: "r"(dst), "l"(src), "r"(bytes), "r"(mbar) : "memory");
}
__device__ __forceinline__ void mma_tf32(
    float acc[4], uint32_t a0, uint32_t a1, uint32_t a2, uint32_t a3,
    uint32_t b0, uint32_t b1)
{
    asm volatile(
        "mma.sync.aligned.m16n8k8.row.col.f32.tf32.tf32.f32 "
        "{%0,%1,%2,%3}, {%4,%5,%6,%7}, {%8,%9}, {%0,%1,%2,%3};\n"
        : "+f"(acc[0]), "+f"(acc[1]), "+f"(acc[2]), "+f"(acc[3])
        : "r"(a0), "r"(a1), "r"(a2), "r"(a3), "r"(b0), "r"(b1));
}

__global__ __launch_bounds__(256) void project_kernel(
    const float* __restrict__ emb,
    const float* __restrict__ Vw)
{
    extern __shared__ float smem[];
    const uint32_t mbarBase = smem_u32(smem + MBAR_OFF);

    const int tid  = threadIdx.x;
    const int warp = tid >> 5;
    const int lane = tid & 31;
    const int g4   = lane >> 2;
    const int tg   = lane & 3;

    const int warpRow = warp >> 2;            // 0..1 -> rows 0-15 / 16-31
    const int colQuad = warp & 3;             // 0..3 -> 8-col group
    const int aRow    = warpRow * 16 + g4;

    if (tid == 0) {
        #pragma unroll
        for (int i = 0; i < NSTAGE; i++) mbar_init(mbarBase + i * 8, 1);
        asm volatile("fence.proxy.async.shared::cta;" ::: "memory");
    }
    if (tid < PAD_ELEMS)                       // zero the overflow pad once
        smem[NSTAGE * TILE_ELEMS + tid] = 0.0f;
    __syncthreads();

    const int bid = blockIdx.x;

    // prologue: fill all 5 stages (tiles bid, bid+148, ..., bid+4*148)
    if (tid == 0) {
        #pragma unroll
        for (int s = 0; s < NSTAGE; s++) {
            int tt = bid + s * GRID;
            if (tt < NT32) {
                mbar_expect_tx(mbarBase + s * 8, TILE_BYTES);
                bulk_copy(smem_u32(smem + s * TILE_ELEMS),
                          emb + (size_t)tt * TILE_ELEMS, TILE_BYTES,
                          mbarBase + s * 8);
            }
        }
    }

    // ---- B fragments straight from gmem into registers (once) ----
    // breg[ks] = {bits(Vw[n][k]), bits(Vw[n][k+4])}, n = colQuad*8 + g4,
    // k = ks*8 + tg. 39 KB total across the grid; L2-cached.
    uint2 breg[KSTEPS];
    {
        const int n = colQuad * 8 + g4;
        const float* vwr = Vw + n * DIM;
        #pragma unroll
        for (int ks = 0; ks < KSTEPS; ks++) {
            int k = ks * 8 + tg;
            breg[ks].x = (k     < DIM) ? __float_as_uint(vwr[k])     : 0u;
            breg[ks].y = (k + 4 < DIM) ? __float_as_uint(vwr[k + 4]) : 0u;
        }
    }

    // per-slot phase bits (compile-time slot ids via unroll-by-5)
    uint32_t ph0 = 0, ph1 = 0, ph2 = 0, ph3 = 0, ph4 = 0;

    int t = bid;
    while (t < NT32) {
        #pragma unroll
        for (int s = 0; s < NSTAGE; s++) {
            if (t < NT32) {
                const uint32_t mb = mbarBase + s * 8;
                uint32_t phv = (s == 0) ? ph0 : (s == 1) ? ph1 : (s == 2) ? ph2
                             : (s == 3) ? ph3 : ph4;
                mbar_wait(mb, phv);
                if      (s == 0) ph0 ^= 1;
                else if (s == 1) ph1 ^= 1;
                else if (s == 2) ph2 ^= 1;
                else if (s == 3) ph3 ^= 1;
                else             ph4 ^= 1;

                const uint32_t* A =
                    (const uint32_t*)(smem + s * TILE_ELEMS) + aRow * DIM + tg;

                // 2 independent chains: even/odd K phases
                float accE[4] = {0.f, 0.f, 0.f, 0.f};
                float accO[4] = {0.f, 0.f, 0.f, 0.f};

                #pragma unroll
                for (int ks = 0; ks < KSTEPS; ks += 2) {
                    {
                        const uint32_t* Ap = A + ks * 8;
                        mma_tf32(accE, Ap[0], Ap[8 * DIM], Ap[4], Ap[8 * DIM + 4],
                                 breg[ks].x, breg[ks].y);
                    }
                    {
                        const uint32_t* Ap = A + (ks + 1) * 8;
                        mma_tf32(accO, Ap[0], Ap[8 * DIM], Ap[4], Ap[8 * DIM + 4],
                                 breg[ks + 1].x, breg[ks + 1].y);
                    }
                }
                // (ks=37 tail reads spill <=7 floats into the next stage /
                //  zeroed pad: finite values x B=0 -> contributes 0.)

                // store 16x8 per warp (float2 stores)
                int r0  = t * TILE_R + warpRow * 16 + g4;
                int col = colQuad * 8 + tg * 2;
                *(float2*)&g_E2[(size_t)r0 * HID + col] =
                    make_float2(accE[0] + accO[0], accE[1] + accO[1]);
                *(float2*)&g_E2[(size_t)(r0 + 8) * HID + col] =
                    make_float2(accE[2] + accO[2], accE[3] + accO[3]);

                __syncthreads();                 // stage s consumed by all warps

                // refill stage s with tile t + 5*GRID
                int tload = t + NSTAGE * GRID;
                if (tid == 0 && tload < NT32) {
                    mbar_expect_tx(mb, TILE_BYTES);
                    bulk_copy(smem_u32(smem + s * TILE_ELEMS),
                              emb + (size_t)tload * TILE_ELEMS, TILE_BYTES, mb);
                }
                t += GRID;
            }
        }
    }
}

// ---------------------------------------------------------------------------
// Pass B: gather E2 rows, mean-pool, relu MLP head -> logits.
// One warp per batch row; lane = hidden unit. 128B coalesced gathers.
// ---------------------------------------------------------------------------
__global__ __launch_bounds__(256) void gather_kernel(
    const int*   __restrict__ tokens,
    const float* __restrict__ Vb,
    const float* __restrict__ Ww,
    const float* __restrict__ Wb,
    float*       __restrict__ out)
{
    const int b    = blockIdx.x * 8 + (threadIdx.x >> 5);
    const int lane = threadIdx.x & 31;

    int t0 = tokens[b * SEQ + lane];
    int t1 = (lane < SEQ - 32) ? tokens[b * SEQ + 32 + lane] : 0;

    float acc = 0.f;
    #pragma unroll
    for (int k = 0; k < SEQ; k++) {
        int tok = (k < 32) ? __shfl_sync(0xffffffffu, t0, k)
                           : __shfl_sync(0xffffffffu, t1, k - 32);
        acc += __ldg(&g_E2[(size_t)tok * HID + lane]);
    }

    float h  = fmaxf(acc * (1.0f / (float)SEQ) + Vb[lane], 0.f);
    float p0 = h * Ww[lane];          // Ww[0][lane]
    float p1 = h * Ww[HID + lane];    // Ww[1][lane]
    #pragma unroll
    for (int off = 16; off; off >>= 1) {
        p0 += __shfl_xor_sync(0xffffffffu, p0, off);
        p1 += __shfl_xor_sync(0xffffffffu, p1, off);
    }
    if (lane == 0) {
        out[b * OUTC + 0] = p0 + Wb[0];
        out[b * OUTC + 1] = p1 + Wb[1];
    }
}

// ---------------------------------------------------------------------------
// Pass C: column-wise logsumexp over the batch axis + in-place subtract.
// Single CTA (fused lse + apply).
// ---------------------------------------------------------------------------
__global__ __launch_bounds__(1024) void lse_apply_kernel(float* __restrict__ logits)
{
    __shared__ float2 red[1024];
    const int tid = threadIdx.x;

    float m0 = -1e30f, m1 = -1e30f;
    for (int r = tid; r < BATCH; r += 1024) {
        float2 v = reinterpret_cast<const float2*>(logits)[r];
        m0 = fmaxf(m0, v.x);
        m1 = fmaxf(m1, v.y);
    }
    red[tid] = make_float2(m0, m1);
    __syncthreads();
    for (int s = 512; s; s >>= 1) {
        if (tid < s) {
            red[tid].x = fmaxf(red[tid].x, red[tid + s].x);
            red[tid].y = fmaxf(red[tid].y, red[tid + s].y);
        }
        __syncthreads();
    }
    m0 = red[0].x; m1 = red[0].y;
    __syncthreads();

    float s0 = 0.f, s1 = 0.f;
    for (int r = tid; r < BATCH; r += 1024) {
        float2 v = reinterpret_cast<const float2*>(logits)[r];
        s0 += expf(v.x - m0);
        s1 += expf(v.y - m1);
    }
    red[tid] = make_float2(s0, s1);
    __syncthreads();
    for (int s = 512; s; s >>= 1) {
        if (tid < s) {
            red[tid].x += red[tid + s].x;
            red[tid].y += red[tid + s].y;
        }
        __syncthreads();
    }
    __syncthreads();
    const float l0 = m0 + logf(red[0].x);
    const float l1 = m1 + logf(red[0].y);

    for (int r = tid; r < BATCH; r += 1024) {
        float2 v = reinterpret_cast<float2*>(logits)[r];
        v.x -= l0;
        v.y -= l1;
        reinterpret_cast<float2*>(logits)[r] = v;
    }
}

extern "C" void kernel_launch(void* const* d_in, const int* in_sizes, int n_in,
                              void* d_out, int out_size)
{
    const int*   tokens = (const int*)  d_in[0];
    const float* emb    = (const float*)d_in[1];
    const float* Vw     = (const float*)d_in[2];
    const float* Vb     = (const float*)d_in[3];
    const float* Ww     = (const float*)d_in[4];
    const float* Wb     = (const float*)d_in[5];
    float* out = (float*)d_out;

    cudaFuncSetAttribute(project_kernel,
                         cudaFuncAttributeMaxDynamicSharedMemorySize, SMEM_BYTES);

    project_kernel<<<GRID, 256, SMEM_BYTES>>>(emb, Vw);
    gather_kernel<<<BATCH / 8, 256>>>(tokens, Vb, Ww, Wb, out);
    lse_apply_kernel<<<1, 1024>>>(out);
}

// round 10
// speedup vs baseline: 1.6047x; 1.0933x over previous
#include <cuda_runtime.h>
#include <cuda_bf16.h>
#include <math.h>
#include <stdint.h>

#define BATCH 16384
#define SEQ   50
#define DIM   300
#define HID   32
#define OUTC  2
#define VOCAB 400000

// allocation-free scratch: E2 as bf16 (packed bf16x2), 16 uints per row
__device__ uint32_t g_E2[(size_t)VOCAB * (HID / 2)];   // 25.6 MB

// ---------------------------------------------------------------------------
// Pass A: E2[v][j] = sum_d emb[v][d] * Vw[j][d]   (400000x300 @ 300x32)
// tf32 mma.sync m16n8k8, raw fp32 bits as tf32. 5-stage cp.async.bulk ring,
// 148 persistent CTAs x 256 threads, 32-row tiles, B fragments in registers.
// R10: result stored as bf16x2 (rn) -> halves project write traffic AND
// gather read traffic.
// ---------------------------------------------------------------------------
#define TILE_R     32
#define KSTEPS     38                        // ceil(300/8); k>=300 -> B=0
#define NT32       (VOCAB / TILE_R)          // 12500 tiles
#define GRID       148
#define NSTAGE     5
#define TILE_ELEMS (TILE_R * DIM)            // 9600 floats
#define TILE_BYTES (TILE_ELEMS * 4)          // 38400 B
#define PAD_ELEMS  16
#define MBAR_OFF   (NSTAGE * TILE_ELEMS + PAD_ELEMS)
#define SMEM_BYTES ((MBAR_OFF + 10) * 4)

__device__ __forceinline__ uint32_t smem_u32(const void* p) {
    return (uint32_t)__cvta_generic_to_shared(p);
}
__device__ __forceinline__ void mbar_init(uint32_t mbar, uint32_t cnt) {
    asm volatile("mbarrier.init.shared::cta.b64 [%0], %1;" :: "r"(mbar), "r"(cnt) : "memory");
}
__device__ __forceinline__ void mbar_expect_tx(uint32_t mbar, uint32_t bytes) {
    asm volatile("mbarrier.arrive.expect_tx.shared::cta.b64 _, [%0], %1;"
                 :: "r"(mbar), "r"(bytes) : "memory");
}
__device__ __forceinline__ void mbar_wait(uint32_t mbar, uint32_t parity) {
    asm volatile(
        "{\n\t"
        ".reg .pred P;\n\t"
        "WAIT_%=: \n\t"
        "mbarrier.try_wait.parity.acquire.cta.shared::cta.b64 P, [%0], %1, 0x989680;\n\t"
        "@P bra.uni DONE_%=;\n\t"
        "bra.uni WAIT_%=;\n\t"
        "DONE_%=: \n\t"
        "}"
        :: "r"(mbar), "r"(parity) : "memory");
}
__device__ __forceinline__ void bulk_copy(uint32_t dst, const void* src,
                                          uint32_t bytes, uint32_t mbar) {
    asm volatile(
        "cp.async.bulk.shared::cta.global.mbarrier::complete_tx::bytes "
        "[%0], [%1], %2, [%3];"
        :: "r"(dst), "l"(src), "r"(bytes), "r"(mbar) : "memory");
}
__device__ __forceinline__ void mma_tf32(
    float acc[4], uint32_t a0, uint32_t a1, uint32_t a2, uint32_t a3,
    uint32_t b0, uint32_t b1)
{
    asm volatile(
        "mma.sync.aligned.m16n8k8.row.col.f32.tf32.tf32.f32 "
        "{%0,%1,%2,%3}, {%4,%5,%6,%7}, {%8,%9}, {%0,%1,%2,%3};\n"
        : "+f"(acc[0]), "+f"(acc[1]), "+f"(acc[2]), "+f"(acc[3])
        : "r"(a0), "r"(a1), "r"(a2), "r"(a3), "r"(b0), "r"(b1));
}
__device__ __forceinline__ uint32_t pack_bf16x2(float lo, float hi) {
    __nv_bfloat162 v = __float22bfloat162_rn(make_float2(lo, hi));
    return *reinterpret_cast<uint32_t*>(&v);
}

__global__ __launch_bounds__(256) void project_kernel(
    const float* __restrict__ emb,
    const float* __restrict__ Vw)
{
    extern __shared__ float smem[];
    const uint32_t mbarBase = smem_u32(smem + MBAR_OFF);

    const int tid  = threadIdx.x;
    const int warp = tid >> 5;
    const int lane = tid & 31;
    const int g4   = lane >> 2;
    const int tg   = lane & 3;

    const int warpRow = warp >> 2;            // 0..1
    const int colQuad = warp & 3;             // 0..3
    const int aRow    = warpRow * 16 + g4;

    if (tid == 0) {
        #pragma unroll
        for (int i = 0; i < NSTAGE; i++) mbar_init(mbarBase + i * 8, 1);
        asm volatile("fence.proxy.async.shared::cta;" ::: "memory");
    }
    if (tid < PAD_ELEMS)
        smem[NSTAGE * TILE_ELEMS + tid] = 0.0f;
    __syncthreads();

    const int bid = blockIdx.x;

    if (tid == 0) {
        #pragma unroll
        for (int s = 0; s < NSTAGE; s++) {
            int tt = bid + s * GRID;
            if (tt < NT32) {
                mbar_expect_tx(mbarBase + s * 8, TILE_BYTES);
                bulk_copy(smem_u32(smem + s * TILE_ELEMS),
                          emb + (size_t)tt * TILE_ELEMS, TILE_BYTES,
                          mbarBase + s * 8);
            }
        }
    }

    // B fragments straight from gmem into registers (once)
    uint2 breg[KSTEPS];
    {
        const int n = colQuad * 8 + g4;
        const float* vwr = Vw + n * DIM;
        #pragma unroll
        for (int ks = 0; ks < KSTEPS; ks++) {
            int k = ks * 8 + tg;
            breg[ks].x = (k     < DIM) ? __float_as_uint(vwr[k])     : 0u;
            breg[ks].y = (k + 4 < DIM) ? __float_as_uint(vwr[k + 4]) : 0u;
        }
    }

    uint32_t ph0 = 0, ph1 = 0, ph2 = 0, ph3 = 0, ph4 = 0;

    int t = bid;
    while (t < NT32) {
        #pragma unroll
        for (int s = 0; s < NSTAGE; s++) {
            if (t < NT32) {
                const uint32_t mb = mbarBase + s * 8;
                uint32_t phv = (s == 0) ? ph0 : (s == 1) ? ph1 : (s == 2) ? ph2
                             : (s == 3) ? ph3 : ph4;
                mbar_wait(mb, phv);
                if      (s == 0) ph0 ^= 1;
                else if (s == 1) ph1 ^= 1;
                else if (s == 2) ph2 ^= 1;
                else if (s == 3) ph3 ^= 1;
                else             ph4 ^= 1;

                const uint32_t* A =
                    (const uint32_t*)(smem + s * TILE_ELEMS) + aRow * DIM + tg;

                float accE[4] = {0.f, 0.f, 0.f, 0.f};
                float accO[4] = {0.f, 0.f, 0.f, 0.f};

                #pragma unroll
                for (int ks = 0; ks < KSTEPS; ks += 2) {
                    {
                        const uint32_t* Ap = A + ks * 8;
                        mma_tf32(accE, Ap[0], Ap[8 * DIM], Ap[4], Ap[8 * DIM + 4],
                                 breg[ks].x, breg[ks].y);
                    }
                    {
                        const uint32_t* Ap = A + (ks + 1) * 8;
                        mma_tf32(accO, Ap[0], Ap[8 * DIM], Ap[4], Ap[8 * DIM + 4],
                                 breg[ks + 1].x, breg[ks + 1].y);
                    }
                }

                // store 16x8 per warp as bf16x2 (one uint per lane per row)
                int r0  = t * TILE_R + warpRow * 16 + g4;
                int cp  = colQuad * 4 + tg;           // uint index within row
                g_E2[(size_t)r0 * (HID / 2) + cp] =
                    pack_bf16x2(accE[0] + accO[0], accE[1] + accO[1]);
                g_E2[(size_t)(r0 + 8) * (HID / 2) + cp] =
                    pack_bf16x2(accE[2] + accO[2], accE[3] + accO[3]);

                __syncthreads();

                int tload = t + NSTAGE * GRID;
                if (tid == 0 && tload < NT32) {
                    mbar_expect_tx(mb, TILE_BYTES);
                    bulk_copy(smem_u32(smem + s * TILE_ELEMS),
                              emb + (size_t)tload * TILE_ELEMS, TILE_BYTES, mb);
                }
                t += GRID;
            }
        }
    }
}

// ---------------------------------------------------------------------------
// Pass B: gather bf16 E2 rows, mean-pool, relu MLP head -> logits.
// One warp per batch row. Warp processes 2 tokens/step: half-warp h reads
// token 2i+h, 16 lanes x bf16x2 = 64B coalesced. 25 steps, then cross-half
// shfl combine and 16-lane head reduction.
// ---------------------------------------------------------------------------
__global__ __launch_bounds__(256) void gather_kernel(
    const int*   __restrict__ tokens,
    const float* __restrict__ Vb,
    const float* __restrict__ Ww,
    const float* __restrict__ Wb,
    float*       __restrict__ out)
{
    const int b    = blockIdx.x * 8 + (threadIdx.x >> 5);
    const int lane = threadIdx.x & 31;
    const int half = lane >> 4;          // 0/1: which token of the pair
    const int hp   = lane & 15;          // hid pair index (hids 2hp, 2hp+1)

    int t0 = tokens[b * SEQ + lane];                              // tokens 0..31
    int t1 = (lane < SEQ - 32) ? tokens[b * SEQ + 32 + lane] : 0; // tokens 32..49

    float2 acc = make_float2(0.f, 0.f);
    #pragma unroll
    for (int i = 0; i < SEQ / 2; i++) {
        const int idx0 = 2 * i, idx1 = 2 * i + 1;   // compile-time after unroll
        int tokA = (idx0 < 32) ? __shfl_sync(0xffffffffu, t0, idx0)
                               : __shfl_sync(0xffffffffu, t1, idx0 - 32);
        int tokB = (idx1 < 32) ? __shfl_sync(0xffffffffu, t0, idx1)
                               : __shfl_sync(0xffffffffu, t1, idx1 - 32);
        int tok = half ? tokB : tokA;
        uint32_t raw = __ldg(&g_E2[(size_t)tok * (HID / 2) + hp]);
        __nv_bfloat162 bv = *reinterpret_cast<__nv_bfloat162*>(&raw);
        float2 fv = __bfloat1622float2(bv);
        acc.x += fv.x;
        acc.y += fv.y;
    }

    // combine the two halves (each summed 25 tokens)
    acc.x += __shfl_xor_sync(0xffffffffu, acc.x, 16);
    acc.y += __shfl_xor_sync(0xffffffffu, acc.y, 16);

    const float inv = 1.0f / (float)SEQ;
    float hx = fmaxf(acc.x * inv + Vb[2 * hp],     0.f);
    float hy = fmaxf(acc.y * inv + Vb[2 * hp + 1], 0.f);

    float p0 = hx * Ww[2 * hp]       + hy * Ww[2 * hp + 1];
    float p1 = hx * Ww[HID + 2 * hp] + hy * Ww[HID + 2 * hp + 1];
    #pragma unroll
    for (int off = 8; off; off >>= 1) {
        p0 += __shfl_xor_sync(0xffffffffu, p0, off);
        p1 += __shfl_xor_sync(0xffffffffu, p1, off);
    }
    if (lane == 0) {
        out[b * OUTC + 0] = p0 + Wb[0];
        out[b * OUTC + 1] = p1 + Wb[1];
    }
}

// ---------------------------------------------------------------------------
// Pass C: column-wise logsumexp over the batch axis + in-place subtract.
// Single CTA (fused lse + apply).
// ---------------------------------------------------------------------------
__global__ __launch_bounds__(1024) void lse_apply_kernel(float* __restrict__ logits)
{
    __shared__ float2 red[1024];
    const int tid = threadIdx.x;

    float m0 = -1e30f, m1 = -1e30f;
    for (int r = tid; r < BATCH; r += 1024) {
        float2 v = reinterpret_cast<const float2*>(logits)[r];
        m0 = fmaxf(m0, v.x);
        m1 = fmaxf(m1, v.y);
    }
    red[tid] = make_float2(m0, m1);
    __syncthreads();
    for (int s = 512; s; s >>= 1) {
        if (tid < s) {
            red[tid].x = fmaxf(red[tid].x, red[tid + s].x);
            red[tid].y = fmaxf(red[tid].y, red[tid + s].y);
        }
        __syncthreads();
    }
    m0 = red[0].x; m1 = red[0].y;
    __syncthreads();

    float s0 = 0.f, s1 = 0.f;
    for (int r = tid; r < BATCH; r += 1024) {
        float2 v = reinterpret_cast<const float2*>(logits)[r];
        s0 += expf(v.x - m0);
        s1 += expf(v.y - m1);
    }
    red[tid] = make_float2(s0, s1);
    __syncthreads();
    for (int s = 512; s; s >>= 1) {
        if (tid < s) {
            red[tid].x += red[tid + s].x;
            red[tid].y += red[tid + s].y;
        }
        __syncthreads();
    }
    __syncthreads();
    const float l0 = m0 + logf(red[0].x);
    const float l1 = m1 + logf(red[0].y);

    for (int r = tid; r < BATCH; r += 1024) {
        float2 v = reinterpret_cast<float2*>(logits)[r];
        v.x -= l0;
        v.y -= l1;
        reinterpret_cast<float2*>(logits)[r] = v;
    }
}

extern "C" void kernel_launch(void* const* d_in, const int* in_sizes, int n_in,
                              void* d_out, int out_size)
{
    const int*   tokens = (const int*)  d_in[0];
    const float* emb    = (const float*)d_in[1];
    const float* Vw     = (const float*)d_in[2];
    const float* Vb     = (const float*)d_in[3];
    const float* Ww     = (const float*)d_in[4];
    const float* Wb     = (const float*)d_in[5];
    float* out = (float*)d_out;

    cudaFuncSetAttribute(project_kernel,
                         cudaFuncAttributeMaxDynamicSharedMemorySize, SMEM_BYTES);

    project_kernel<<<GRID, 256, SMEM_BYTES>>>(emb, Vw);
    gather_kernel<<<BATCH / 8, 256>>>(tokens, Vb, Ww, Wb, out);
    lse_apply_kernel<<<1, 1024>>>(out);
}

// round 11
// speedup vs baseline: 1.6380x; 1.0207x over previous
#include <cuda_runtime.h>
#include <cuda_bf16.h>
#include <math.h>
#include <stdint.h>

#define BATCH 16384
#define SEQ   50
#define DIM   300
#define HID   32
#define OUTC  2
#define VOCAB 400000

// allocation-free scratch
__device__ uint32_t g_E2[(size_t)VOCAB * (HID / 2)];   // bf16x2 table, 25.6 MB
__device__ float4   g_part[BATCH / 8];                 // per-CTA {m0,m1,s0,s1}

// ---------------------------------------------------------------------------
// Pass A: E2[v][j] = sum_d emb[v][d] * Vw[j][d]   (400000x300 @ 300x32)
// tf32 mma.sync m16n8k8, raw fp32 bits as tf32. 5-stage cp.async.bulk ring,
// 148 persistent CTAs x 256 threads, 32-row tiles, B fragments in registers,
// bf16x2 output.
// R11: per-stage EMPTY mbarriers (arrive-count 8, one arrive per warp)
// replace the CTA-wide __syncthreads -> fast warps proceed to the next full
// stage immediately; producer refills a stage when its 8 consumers arrived.
// ---------------------------------------------------------------------------
#define TILE_R     32
#define KSTEPS     38                        // ceil(300/8); k>=300 -> B=0
#define NT32       (VOCAB / TILE_R)          // 12500 tiles
#define GRID       148
#define NSTAGE     5
#define TILE_ELEMS (TILE_R * DIM)            // 9600 floats
#define TILE_BYTES (TILE_ELEMS * 4)          // 38400 B
#define PAD_ELEMS  16
#define MBAR_OFF   (NSTAGE * TILE_ELEMS + PAD_ELEMS)   // float idx, 16B aligned
#define SMEM_BYTES ((MBAR_OFF + 20) * 4)               // 10 mbarriers (80 B)

__device__ __forceinline__ uint32_t smem_u32(const void* p) {
    return (uint32_t)__cvta_generic_to_shared(p);
}
__device__ __forceinline__ void mbar_init(uint32_t mbar, uint32_t cnt) {
    asm volatile("mbarrier.init.shared::cta.b64 [%0], %1;" :: "r"(mbar), "r"(cnt) : "memory");
}
__device__ __forceinline__ void mbar_expect_tx(uint32_t mbar, uint32_t bytes) {
    asm volatile("mbarrier.arrive.expect_tx.shared::cta.b64 _, [%0], %1;"
                 :: "r"(mbar), "r"(bytes) : "memory");
}
__device__ __forceinline__ void mbar_arrive(uint32_t mbar) {
    asm volatile("mbarrier.arrive.release.cta.shared::cta.b64 _, [%0];"
                 :: "r"(mbar) : "memory");
}
__device__ __forceinline__ void mbar_wait(uint32_t mbar, uint32_t parity) {
    asm volatile(
        "{\n\t"
        ".reg .pred P;\n\t"
        "WAIT_%=: \n\t"
        "mbarrier.try_wait.parity.acquire.cta.shared::cta.b64 P, [%0], %1, 0x989680;\n\t"
        "@P bra.uni DONE_%=;\n\t"
        "bra.uni WAIT_%=;\n\t"
        "DONE_%=: \n\t"
        "}"
        :: "r"(mbar), "r"(parity) : "memory");
}
__device__ __forceinline__ void bulk_copy(uint32_t dst, const void* src,
                                          uint32_t bytes, uint32_t mbar) {
    asm volatile(
        "cp.async.bulk.shared::cta.global.mbarrier::complete_tx::bytes "
        "[%0], [%1], %2, [%3];"
        :: "r"(dst), "l"(src), "r"(bytes), "r"(mbar) : "memory");
}
__device__ __forceinline__ void mma_tf32(
    float acc[4], uint32_t a0, uint32_t a1, uint32_t a2, uint32_t a3,
    uint32_t b0, uint32_t b1)
{
    asm volatile(
        "mma.sync.aligned.m16n8k8.row.col.f32.tf32.tf32.f32 "
        "{%0,%1,%2,%3}, {%4,%5,%6,%7}, {%8,%9}, {%0,%1,%2,%3};\n"
        : "+f"(acc[0]), "+f"(acc[1]), "+f"(acc[2]), "+f"(acc[3])
        : "r"(a0), "r"(a1), "r"(a2), "r"(a3), "r"(b0), "r"(b1));
}
__device__ __forceinline__ uint32_t pack_bf16x2(float lo, float hi) {
    __nv_bfloat162 v = __float22bfloat162_rn(make_float2(lo, hi));
    return *reinterpret_cast<uint32_t*>(&v);
}

__global__ __launch_bounds__(256) void project_kernel(
    const float* __restrict__ emb,
    const float* __restrict__ Vw)
{
    extern __shared__ float smem[];
    const uint32_t mbarBase = smem_u32(smem + MBAR_OFF);   // full[0..4]
    const uint32_t emptyBase = mbarBase + NSTAGE * 8;      // empty[0..4]

    const int tid  = threadIdx.x;
    const int warp = tid >> 5;
    const int lane = tid & 31;
    const int g4   = lane >> 2;
    const int tg   = lane & 3;

    const int warpRow = warp >> 2;            // 0..1
    const int colQuad = warp & 3;             // 0..3
    const int aRow    = warpRow * 16 + g4;

    if (tid == 0) {
        #pragma unroll
        for (int i = 0; i < NSTAGE; i++) {
            mbar_init(mbarBase  + i * 8, 1);   // full: tx-based
            mbar_init(emptyBase + i * 8, 8);   // empty: 8 warp arrivals
        }
        asm volatile("fence.proxy.async.shared::cta;" ::: "memory");
    }
    if (tid < PAD_ELEMS)
        smem[NSTAGE * TILE_ELEMS + tid] = 0.0f;
    __syncthreads();

    const int bid = blockIdx.x;

    if (tid == 0) {
        #pragma unroll
        for (int s = 0; s < NSTAGE; s++) {
            int tt = bid + s * GRID;
            if (tt < NT32) {
                mbar_expect_tx(mbarBase + s * 8, TILE_BYTES);
                bulk_copy(smem_u32(smem + s * TILE_ELEMS),
                          emb + (size_t)tt * TILE_ELEMS, TILE_BYTES,
                          mbarBase + s * 8);
            }
        }
    }

    // B fragments straight from gmem into registers (once)
    uint2 breg[KSTEPS];
    {
        const int n = colQuad * 8 + g4;
        const float* vwr = Vw + n * DIM;
        #pragma unroll
        for (int ks = 0; ks < KSTEPS; ks++) {
            int k = ks * 8 + tg;
            breg[ks].x = (k     < DIM) ? __float_as_uint(vwr[k])     : 0u;
            breg[ks].y = (k + 4 < DIM) ? __float_as_uint(vwr[k + 4]) : 0u;
        }
    }

    uint32_t ph0 = 0, ph1 = 0, ph2 = 0, ph3 = 0, ph4 = 0;   // full parities
    uint32_t pe0 = 0, pe1 = 0, pe2 = 0, pe3 = 0, pe4 = 0;   // empty parities

    int t = bid;
    while (t < NT32) {
        #pragma unroll
        for (int s = 0; s < NSTAGE; s++) {
            if (t < NT32) {
                const uint32_t fullb  = mbarBase  + s * 8;
                const uint32_t emptyb = emptyBase + s * 8;

                uint32_t phv = (s == 0) ? ph0 : (s == 1) ? ph1 : (s == 2) ? ph2
                             : (s == 3) ? ph3 : ph4;
                mbar_wait(fullb, phv);
                if      (s == 0) ph0 ^= 1;
                else if (s == 1) ph1 ^= 1;
                else if (s == 2) ph2 ^= 1;
                else if (s == 3) ph3 ^= 1;
                else             ph4 ^= 1;

                const uint32_t* A =
                    (const uint32_t*)(smem + s * TILE_ELEMS) + aRow * DIM + tg;

                float accE[4] = {0.f, 0.f, 0.f, 0.f};
                float accO[4] = {0.f, 0.f, 0.f, 0.f};

                #pragma unroll
                for (int ks = 0; ks < KSTEPS; ks += 2) {
                    {
                        const uint32_t* Ap = A + ks * 8;
                        mma_tf32(accE, Ap[0], Ap[8 * DIM], Ap[4], Ap[8 * DIM + 4],
                                 breg[ks].x, breg[ks].y);
                    }
                    {
                        const uint32_t* Ap = A + (ks + 1) * 8;
                        mma_tf32(accO, Ap[0], Ap[8 * DIM], Ap[4], Ap[8 * DIM + 4],
                                 breg[ks + 1].x, breg[ks + 1].y);
                    }
                }

                // all this warp's smem reads for stage s are consumed by the
                // issued MMAs (in-order issue) -> safe to signal empty now
                if (lane == 0) mbar_arrive(emptyb);

                // store 16x8 per warp as bf16x2
                int r0  = t * TILE_R + warpRow * 16 + g4;
                int cp  = colQuad * 4 + tg;
                g_E2[(size_t)r0 * (HID / 2) + cp] =
                    pack_bf16x2(accE[0] + accO[0], accE[1] + accO[1]);
                g_E2[(size_t)(r0 + 8) * (HID / 2) + cp] =
                    pack_bf16x2(accE[2] + accO[2], accE[3] + accO[3]);

                // producer: refill stage s once all 8 warps arrived
                int tload = t + NSTAGE * GRID;
                if (tid == 0 && tload < NT32) {
                    uint32_t pev = (s == 0) ? pe0 : (s == 1) ? pe1 : (s == 2) ? pe2
                                 : (s == 3) ? pe3 : pe4;
                    mbar_wait(emptyb, pev);
                    if      (s == 0) pe0 ^= 1;
                    else if (s == 1) pe1 ^= 1;
                    else if (s == 2) pe2 ^= 1;
                    else if (s == 3) pe3 ^= 1;
                    else             pe4 ^= 1;
                    mbar_expect_tx(fullb, TILE_BYTES);
                    bulk_copy(smem_u32(smem + s * TILE_ELEMS),
                              emb + (size_t)tload * TILE_ELEMS, TILE_BYTES, fullb);
                }
                t += GRID;
            }
        }
    }
}

// ---------------------------------------------------------------------------
// Pass B: gather bf16 E2 rows, mean-pool, relu MLP head -> logits
// + per-CTA online-LSE partial {max, expsum} written to g_part (fixed-order
// reductions -> deterministic).
// ---------------------------------------------------------------------------
__global__ __launch_bounds__(256) void gather_kernel(
    const int*   __restrict__ tokens,
    const float* __restrict__ Vb,
    const float* __restrict__ Ww,
    const float* __restrict__ Wb,
    float*       __restrict__ out)
{
    __shared__ float2 sE[8];

    const int warp = threadIdx.x >> 5;
    const int b    = blockIdx.x * 8 + warp;
    const int lane = threadIdx.x & 31;
    const int half = lane >> 4;
    const int hp   = lane & 15;

    int t0 = tokens[b * SEQ + lane];
    int t1 = (lane < SEQ - 32) ? tokens[b * SEQ + 32 + lane] : 0;

    float2 acc = make_float2(0.f, 0.f);
    #pragma unroll
    for (int i = 0; i < SEQ / 2; i++) {
        const int idx0 = 2 * i, idx1 = 2 * i + 1;
        int tokA = (idx0 < 32) ? __shfl_sync(0xffffffffu, t0, idx0)
                               : __shfl_sync(0xffffffffu, t1, idx0 - 32);
        int tokB = (idx1 < 32) ? __shfl_sync(0xffffffffu, t0, idx1)
                               : __shfl_sync(0xffffffffu, t1, idx1 - 32);
        int tok = half ? tokB : tokA;
        uint32_t raw = __ldg(&g_E2[(size_t)tok * (HID / 2) + hp]);
        __nv_bfloat162 bv = *reinterpret_cast<__nv_bfloat162*>(&raw);
        float2 fv = __bfloat1622float2(bv);
        acc.x += fv.x;
        acc.y += fv.y;
    }

    acc.x += __shfl_xor_sync(0xffffffffu, acc.x, 16);
    acc.y += __shfl_xor_sync(0xffffffffu, acc.y, 16);

    const float inv = 1.0f / (float)SEQ;
    float hx = fmaxf(acc.x * inv + Vb[2 * hp],     0.f);
    float hy = fmaxf(acc.y * inv + Vb[2 * hp + 1], 0.f);

    float p0 = hx * Ww[2 * hp]       + hy * Ww[2 * hp + 1];
    float p1 = hx * Ww[HID + 2 * hp] + hy * Ww[HID + 2 * hp + 1];
    #pragma unroll
    for (int off = 8; off; off >>= 1) {
        p0 += __shfl_xor_sync(0xffffffffu, p0, off);
        p1 += __shfl_xor_sync(0xffffffffu, p1, off);
    }

    float e0 = p0 + Wb[0];
    float e1 = p1 + Wb[1];
    if (lane == 0) {
        out[b * OUTC + 0] = e0;
        out[b * OUTC + 1] = e1;
        sE[warp] = make_float2(e0, e1);
    }
    __syncthreads();

    // warp 0, lanes 0-7: per-CTA max + expsum over the 8 rows
    if (warp == 0) {
        float v0 = -1e30f, v1 = -1e30f;
        if (lane < 8) { v0 = sE[lane].x; v1 = sE[lane].y; }
        float m0 = v0, m1 = v1;
        #pragma unroll
        for (int off = 4; off; off >>= 1) {
            m0 = fmaxf(m0, __shfl_xor_sync(0xffffffffu, m0, off));
            m1 = fmaxf(m1, __shfl_xor_sync(0xffffffffu, m1, off));
        }
        float s0 = (lane < 8) ? expf(v0 - m0) : 0.f;
        float s1 = (lane < 8) ? expf(v1 - m1) : 0.f;
        #pragma unroll
        for (int off = 4; off; off >>= 1) {
            s0 += __shfl_xor_sync(0xffffffffu, s0, off);
            s1 += __shfl_xor_sync(0xffffffffu, s1, off);
        }
        if (lane == 0)
            g_part[blockIdx.x] = make_float4(m0, m1, s0, s1);
    }
}

// ---------------------------------------------------------------------------
// Pass C: combine 2048 per-CTA partials -> global LSE, then in-place apply.
// Single CTA, 1024 threads.
// ---------------------------------------------------------------------------
__global__ __launch_bounds__(1024) void lse_apply_kernel(float* __restrict__ logits)
{
    __shared__ float2 redm[1024];
    __shared__ float2 reds[1024];
    const int tid = threadIdx.x;

    float4 a = g_part[tid];
    float4 bpart = g_part[tid + 1024];

    redm[tid] = make_float2(fmaxf(a.x, bpart.x), fmaxf(a.y, bpart.y));
    __syncthreads();
    for (int s = 512; s; s >>= 1) {
        if (tid < s) {
            redm[tid].x = fmaxf(redm[tid].x, redm[tid + s].x);
            redm[tid].y = fmaxf(redm[tid].y, redm[tid + s].y);
        }
        __syncthreads();
    }
    const float M0 = redm[0].x, M1 = redm[0].y;

    float s0 = a.z * expf(a.x - M0) + bpart.z * expf(bpart.x - M0);
    float s1 = a.w * expf(a.y - M1) + bpart.w * expf(bpart.y - M1);
    reds[tid] = make_float2(s0, s1);
    __syncthreads();
    for (int s = 512; s; s >>= 1) {
        if (tid < s) {
            reds[tid].x += reds[tid + s].x;
            reds[tid].y += reds[tid + s].y;
        }
        __syncthreads();
    }
    const float l0 = M0 + logf(reds[0].x);
    const float l1 = M1 + logf(reds[0].y);

    for (int r = tid; r < BATCH; r += 1024) {
        float2 v = reinterpret_cast<float2*>(logits)[r];
        v.x -= l0;
        v.y -= l1;
        reinterpret_cast<float2*>(logits)[r] = v;
    }
}

extern "C" void kernel_launch(void* const* d_in, const int* in_sizes, int n_in,
                              void* d_out, int out_size)
{
    const int*   tokens = (const int*)  d_in[0];
    const float* emb    = (const float*)d_in[1];
    const float* Vw     = (const float*)d_in[2];
    const float* Vb     = (const float*)d_in[3];
    const float* Ww     = (const float*)d_in[4];
    const float* Wb     = (const float*)d_in[5];
    float* out = (float*)d_out;

    cudaFuncSetAttribute(project_kernel,
                         cudaFuncAttributeMaxDynamicSharedMemorySize, SMEM_BYTES);

    project_kernel<<<GRID, 256, SMEM_BYTES>>>(emb, Vw);
    gather_kernel<<<BATCH / 8, 256>>>(tokens, Vb, Ww, Wb, out);
    lse_apply_kernel<<<1, 1024>>>(out);
}